// round 11
// baseline (speedup 1.0000x reference)
#include <cuda_runtime.h>
#include <cuda_bf16.h>
#include <cstdint>

// Problem shape: B=16, N=1024, C=1280, d=160
#define SZ_B   16
#define SZ_N   1024
#define SZ_C   1280
#define SZ_D   160
#define SZ_BN  (SZ_B * SZ_N)

// ---------------------------------------------------------------------------
// Scratch (static __device__ globals)
// ---------------------------------------------------------------------------
__device__ float g_k  [(size_t)SZ_B * SZ_N * SZ_D];
__device__ float g_q  [(size_t)SZ_B * SZ_N * SZ_D];
__device__ float g_v  [(size_t)SZ_B * SZ_N * SZ_C];   // reused for cav
__device__ float g_s  [(size_t)SZ_B * SZ_N * SZ_N];
__device__ float g_s2 [(size_t)SZ_B * SZ_C * SZ_C];
__device__ float g_pav[(size_t)SZ_B * SZ_N * SZ_C];

// ---------------------------------------------------------------------------
// Helpers (all base-target PTX: ldmatrix sm_75+, bf16 mma sm_80+)
// ---------------------------------------------------------------------------
__device__ __forceinline__ uint32_t smem_u32(const void* p) {
    uint32_t a;
    asm("{ .reg .u64 t; cvta.to.shared.u64 t, %1; cvt.u32.u64 %0, t; }"
        : "=r"(a) : "l"(p));
    return a;
}
#define SWZ128(off) ((off) ^ (((off) >> 3) & 0x70))

__device__ __forceinline__ void ldsm4(uint32_t& a0, uint32_t& a1, uint32_t& a2,
                                      uint32_t& a3, uint32_t addr) {
    asm volatile("ldmatrix.sync.aligned.m8n8.x4.shared.b16 {%0,%1,%2,%3}, [%4];"
                 : "=r"(a0), "=r"(a1), "=r"(a2), "=r"(a3) : "r"(addr));
}
__device__ __forceinline__ void ldsm2(uint32_t& b0, uint32_t& b1, uint32_t addr) {
    asm volatile("ldmatrix.sync.aligned.m8n8.x2.shared.b16 {%0,%1}, [%2];"
                 : "=r"(b0), "=r"(b1) : "r"(addr));
}
__device__ __forceinline__ void mma16816(float* c, const uint32_t* a,
                                         const uint32_t* b) {
    asm volatile(
        "mma.sync.aligned.m16n8k16.row.col.f32.bf16.bf16.f32 "
        "{%0,%1,%2,%3}, {%4,%5,%6,%7}, {%8,%9}, {%0,%1,%2,%3};"
        : "+f"(c[0]), "+f"(c[1]), "+f"(c[2]), "+f"(c[3])
        : "r"(a[0]), "r"(a[1]), "r"(a[2]), "r"(a[3]), "r"(b[0]), "r"(b[1]));
}

// fp32 -> (hi, lo) bf16 pair, two at a time (packed bf16x2 words)
__device__ __forceinline__ void cvt_hilo2(float a, float b, uint32_t& h, uint32_t& l) {
    __nv_bfloat16 ha = __float2bfloat16(a);
    __nv_bfloat16 hb = __float2bfloat16(b);
    float ra = a - __bfloat162float(ha);
    float rb = b - __bfloat162float(hb);
    __nv_bfloat162 hp; hp.x = ha; hp.y = hb;
    __nv_bfloat162 lp; lp.x = __float2bfloat16(ra); lp.y = __float2bfloat16(rb);
    h = *reinterpret_cast<uint32_t*>(&hp);
    l = *reinterpret_cast<uint32_t*>(&lp);
}

// ---------------------------------------------------------------------------
// Tensor-core GEMM via mma.sync (bf16 hi/lo 3-term split, fp32 accumulate)
//   C[M, Ncols] = op(A) @ op(B).  CTA tile 128x128, K-chunk 64, 2-stage smem.
//   TA=false: A(m,k)=A[m*lda+k]    TA=true:  A(m,k)=A[k*lda+m]
//   TB=false: B(k,n)=B[k*ldb+n]    TB=true:  B(k,n)=B[n*ldb+k]
//   smem tiles: rows of 64 bf16 (128 B), SW128 swizzle -> conflict-free ldmatrix.
//   M and K tiles always in-bounds for this problem; Ncols may be ragged (160).
// ---------------------------------------------------------------------------
#define A_BYTES 16384              // 128 rows * 128 B
#define STG     65536              // Ah + Al + Bh + Bl per stage

template <bool TA, bool TB>
__global__ __launch_bounds__(256, 1)
void mma_gemm(const float* __restrict__ A, const float* __restrict__ B,
              float* __restrict__ C, int Ncols, int K,
              int lda, int ldb, int ldc, long sA, long sB, long sC)
{
    extern __shared__ char smem[];
    A += (long)blockIdx.z * sA;
    B += (long)blockIdx.z * sB;
    C += (long)blockIdx.z * sC;

    const int tid  = threadIdx.x;
    const int lane = tid & 31;
    const int wid  = tid >> 5;
    const int wm   = wid & 1;        // 2 warp rows  (64 each)
    const int wn   = wid >> 1;       // 4 warp cols  (32 each)
    const int m0   = blockIdx.y * 128;
    const int n0   = blockIdx.x * 128;

    const uint32_t sb = smem_u32(smem);
    const int nch = (K + 63) / 64;

    // ---- loaders: global fp32 -> split bf16 hi/lo -> swizzled smem ----
    auto loadA = [&](int k0, int chunk, int st) {
        char* oAh = smem + st * STG;
        char* oAl = oAh + A_BYTES;
        if (!TA) {
            const int c4n = chunk >> 2;
            for (int idx = tid; idx < 128 * c4n; idx += 256) {
                const int r = idx / c4n, c4 = idx - r * c4n;
                const float4 v = *reinterpret_cast<const float4*>(
                    A + (long)(m0 + r) * lda + k0 + c4 * 4);
                uint32_t h0, l0, h1, l1;
                cvt_hilo2(v.x, v.y, h0, l0);
                cvt_hilo2(v.z, v.w, h1, l1);
                const uint32_t sw = SWZ128((uint32_t)(r * 128 + c4 * 8));
                *reinterpret_cast<uint2*>(oAh + sw) = make_uint2(h0, h1);
                *reinterpret_cast<uint2*>(oAl + sw) = make_uint2(l0, l1);
            }
        } else {
            for (int idx = tid; idx < chunk * 32; idx += 256) {
                const int kk = idx >> 5, m4 = (idx & 31) * 4;
                const float4 v = *reinterpret_cast<const float4*>(
                    A + (long)(k0 + kk) * lda + m0 + m4);
                const float vv[4] = {v.x, v.y, v.z, v.w};
#pragma unroll
                for (int u = 0; u < 4; u++) {
                    const float x = vv[u];
                    const __nv_bfloat16 h = __float2bfloat16(x);
                    const __nv_bfloat16 l = __float2bfloat16(x - __bfloat162float(h));
                    const uint32_t sw = SWZ128((uint32_t)((m4 + u) * 128 + kk * 2));
                    *reinterpret_cast<__nv_bfloat16*>(oAh + sw) = h;
                    *reinterpret_cast<__nv_bfloat16*>(oAl + sw) = l;
                }
            }
        }
    };
    auto loadB = [&](int k0, int chunk, int st) {
        char* oBh = smem + st * STG + 2 * A_BYTES;
        char* oBl = oBh + A_BYTES;
        if (TB) {  // B[n][k], k contiguous
            const int c4n = chunk >> 2;
            for (int idx = tid; idx < 128 * c4n; idx += 256) {
                const int r = idx / c4n, c4 = idx - r * c4n;
                const float4 v = *reinterpret_cast<const float4*>(
                    B + (long)(n0 + r) * ldb + k0 + c4 * 4);
                uint32_t h0, l0, h1, l1;
                cvt_hilo2(v.x, v.y, h0, l0);
                cvt_hilo2(v.z, v.w, h1, l1);
                const uint32_t sw = SWZ128((uint32_t)(r * 128 + c4 * 8));
                *reinterpret_cast<uint2*>(oBh + sw) = make_uint2(h0, h1);
                *reinterpret_cast<uint2*>(oBl + sw) = make_uint2(l0, l1);
            }
        } else {   // B[k][n], transpose into [n][k]; guard ragged Ncols
            for (int idx = tid; idx < chunk * 32; idx += 256) {
                const int kk = idx >> 5, n4 = (idx & 31) * 4;
                float4 v = make_float4(0.f, 0.f, 0.f, 0.f);
                if (n0 + n4 < Ncols)
                    v = *reinterpret_cast<const float4*>(
                        B + (long)(k0 + kk) * ldb + n0 + n4);
                const float vv[4] = {v.x, v.y, v.z, v.w};
#pragma unroll
                for (int u = 0; u < 4; u++) {
                    const float x = vv[u];
                    const __nv_bfloat16 h = __float2bfloat16(x);
                    const __nv_bfloat16 l = __float2bfloat16(x - __bfloat162float(h));
                    const uint32_t sw = SWZ128((uint32_t)((n4 + u) * 128 + kk * 2));
                    *reinterpret_cast<__nv_bfloat16*>(oBh + sw) = h;
                    *reinterpret_cast<__nv_bfloat16*>(oBl + sw) = l;
                }
            }
        }
    };

    float acc[4][4][4];
#pragma unroll
    for (int i = 0; i < 4; i++)
#pragma unroll
        for (int j = 0; j < 4; j++)
#pragma unroll
            for (int u = 0; u < 4; u++) acc[i][j][u] = 0.f;

    // ---- prologue ----
    {
        const int c0 = (K < 64) ? K : 64;
        loadA(0, c0, 0);
        loadB(0, c0, 0);
        __syncthreads();
    }

    // ---- main loop ----
    for (int ch = 0; ch < nch; ch++) {
        const int st = ch & 1;
        const int k0 = ch * 64;
        const int chunk = (K - k0 < 64) ? (K - k0) : 64;
        const int ks = chunk >> 4;

        if (ch + 1 < nch) {
            const int k1 = k0 + 64;
            const int c1 = (K - k1 < 64) ? (K - k1) : 64;
            loadA(k1, c1, st ^ 1);
            loadB(k1, c1, st ^ 1);
        }

        const uint32_t aBh = sb + st * STG;
        const uint32_t aBl = aBh + A_BYTES;
        const uint32_t bBh = aBh + 2 * A_BYTES;
        const uint32_t bBl = aBh + 3 * A_BYTES;

        const int r8 = lane & 7;
        const int bhalf = (lane >> 3) & 1;   // ldmatrix.x2 uses lanes 0-15

        for (int kt = 0; kt < ks; kt++) {
            // B fragments for all 4 n-subtiles (hi and lo)
            uint32_t bh[4][2], bl[4][2];
#pragma unroll
            for (int nt = 0; nt < 4; nt++) {
                const int brow = wn * 32 + nt * 8 + r8;
                const uint32_t boff =
                    SWZ128((uint32_t)(brow * 128 + (2 * kt + bhalf) * 16));
                ldsm2(bh[nt][0], bh[nt][1], bBh + boff);
                ldsm2(bl[nt][0], bl[nt][1], bBl + boff);
            }
            const int g = lane >> 3;
#pragma unroll
            for (int mt = 0; mt < 4; mt++) {
                const int arow = wm * 64 + mt * 16 + (g & 1) * 8 + r8;
                const uint32_t aoff =
                    SWZ128((uint32_t)(arow * 128 + (2 * kt + (g >> 1)) * 16));
                uint32_t ah[4], al[4];
                ldsm4(ah[0], ah[1], ah[2], ah[3], aBh + aoff);
                ldsm4(al[0], al[1], al[2], al[3], aBl + aoff);
#pragma unroll
                for (int nt = 0; nt < 4; nt++) {
                    mma16816(acc[mt][nt], ah, bh[nt]);
                    mma16816(acc[mt][nt], ah, bl[nt]);
                    mma16816(acc[mt][nt], al, bh[nt]);
                }
            }
        }
        __syncthreads();
    }

    // ---- store accumulators ----
#pragma unroll
    for (int mt = 0; mt < 4; mt++) {
#pragma unroll
        for (int nt = 0; nt < 4; nt++) {
            const int row0 = m0 + wm * 64 + mt * 16 + (lane >> 2);
            const int col  = n0 + wn * 32 + nt * 8 + (lane & 3) * 2;
            if (col < Ncols) {
                *reinterpret_cast<float2*>(C + (long)row0 * ldc + col) =
                    make_float2(acc[mt][nt][0], acc[mt][nt][1]);
                *reinterpret_cast<float2*>(C + (long)(row0 + 8) * ldc + col) =
                    make_float2(acc[mt][nt][2], acc[mt][nt][3]);
            }
        }
    }
}

// ---------------------------------------------------------------------------
// Row softmax
// ---------------------------------------------------------------------------
__global__ void softmax_rows(float* __restrict__ data, int L)
{
    float* p = data + (long)blockIdx.x * L;
    const int tid = threadIdx.x;
    __shared__ float red[8];

    float m = -3.402823466e38f;
    for (int i = tid; i < L; i += 256) m = fmaxf(m, p[i]);
#pragma unroll
    for (int o = 16; o; o >>= 1) m = fmaxf(m, __shfl_xor_sync(0xffffffffu, m, o));
    if ((tid & 31) == 0) red[tid >> 5] = m;
    __syncthreads();
    m = red[0];
#pragma unroll
    for (int w = 1; w < 8; w++) m = fmaxf(m, red[w]);

    float s = 0.f;
    for (int i = tid; i < L; i += 256) {
        float e = __expf(p[i] - m);
        p[i] = e;
        s += e;
    }
#pragma unroll
    for (int o = 16; o; o >>= 1) s += __shfl_xor_sync(0xffffffffu, s, o);
    __syncthreads();
    if ((tid & 31) == 0) red[tid >> 5] = s;
    __syncthreads();
    s = 0.f;
#pragma unroll
    for (int w = 0; w < 8; w++) s += red[w];

    const float inv = 1.0f / s;
    for (int i = tid; i < L; i += 256) p[i] *= inv;
}

// ---------------------------------------------------------------------------
// Epilogue: out = gamma*pav + beta*cav + 2*x
// ---------------------------------------------------------------------------
__global__ void epilogue_kernel(const float* __restrict__ x,
                                const float* __restrict__ pav,
                                const float* __restrict__ cav,
                                const float* __restrict__ gamma,
                                const float* __restrict__ beta,
                                float* __restrict__ out, long n4)
{
    long i = (long)blockIdx.x * blockDim.x + threadIdx.x;
    if (i >= n4) return;
    const float g = __ldg(gamma);
    const float bt = __ldg(beta);
    float4 xp = reinterpret_cast<const float4*>(x)[i];
    float4 pp = reinterpret_cast<const float4*>(pav)[i];
    float4 cp = reinterpret_cast<const float4*>(cav)[i];
    float4 o;
    o.x = g * pp.x + bt * cp.x + 2.f * xp.x;
    o.y = g * pp.y + bt * cp.y + 2.f * xp.y;
    o.z = g * pp.z + bt * cp.z + 2.f * xp.z;
    o.w = g * pp.w + bt * cp.w + 2.f * xp.w;
    reinterpret_cast<float4*>(out)[i] = o;
}

// ---------------------------------------------------------------------------
// kernel_launch
// ---------------------------------------------------------------------------
extern "C" void kernel_launch(void* const* d_in, const int* in_sizes, int n_in,
                              void* d_out, int out_size)
{
    const float* x     = (const float*)d_in[0];
    const float* Wk    = (const float*)d_in[1];
    const float* Wq    = (const float*)d_in[2];
    const float* Wv    = (const float*)d_in[3];
    const float* gamma = (const float*)d_in[4];
    const float* beta  = (const float*)d_in[5];
    float* out = (float*)d_out;

    float *k_, *q_, *v_, *s_, *s2_, *pav_;
    cudaGetSymbolAddress((void**)&k_,   g_k);
    cudaGetSymbolAddress((void**)&q_,   g_q);
    cudaGetSymbolAddress((void**)&v_,   g_v);
    cudaGetSymbolAddress((void**)&s_,   g_s);
    cudaGetSymbolAddress((void**)&s2_,  g_s2);
    cudaGetSymbolAddress((void**)&pav_, g_pav);
    float* cav_ = v_;   // v dead after pav GEMM

    constexpr int SMEM = 2 * STG;   // 131072 B
    cudaFuncSetAttribute((const void*)mma_gemm<false, false>,
                         cudaFuncAttributeMaxDynamicSharedMemorySize, SMEM);
    cudaFuncSetAttribute((const void*)mma_gemm<false, true>,
                         cudaFuncAttributeMaxDynamicSharedMemorySize, SMEM);
    cudaFuncSetAttribute((const void*)mma_gemm<true, false>,
                         cudaFuncAttributeMaxDynamicSharedMemorySize, SMEM);

    // k = x @ Wk  [16384,160]
    mma_gemm<false, false><<<dim3(2, 128, 1), 256, SMEM>>>(
        x, Wk, k_, SZ_D, SZ_C, SZ_C, SZ_D, SZ_D, 0, 0, 0);
    // q = x @ Wq
    mma_gemm<false, false><<<dim3(2, 128, 1), 256, SMEM>>>(
        x, Wq, q_, SZ_D, SZ_C, SZ_C, SZ_D, SZ_D, 0, 0, 0);
    // v = x @ Wv  [16384,1280]
    mma_gemm<false, false><<<dim3(10, 128, 1), 256, SMEM>>>(
        x, Wv, v_, SZ_C, SZ_C, SZ_C, SZ_C, SZ_C, 0, 0, 0);

    // s[b] = k[b] @ q[b]^T  (NT, batch 16, K=160)
    mma_gemm<false, true><<<dim3(8, 8, SZ_B), 256, SMEM>>>(
        k_, q_, s_, SZ_N, SZ_D, SZ_D, SZ_D, SZ_N,
        (long)SZ_N * SZ_D, (long)SZ_N * SZ_D, (long)SZ_N * SZ_N);

    softmax_rows<<<SZ_B * SZ_N, 256>>>(s_, SZ_N);

    // pav[b] = p[b] @ v[b]  (NN, batch 16, K=1024)
    mma_gemm<false, false><<<dim3(10, 8, SZ_B), 256, SMEM>>>(
        s_, v_, pav_, SZ_C, SZ_N, SZ_N, SZ_C, SZ_C,
        (long)SZ_N * SZ_N, (long)SZ_N * SZ_C, (long)SZ_N * SZ_C);

    // s2[b] = x[b]^T @ x[b]  (TN, batch 16, K=1024)
    mma_gemm<true, false><<<dim3(10, 10, SZ_B), 256, SMEM>>>(
        x, x, s2_, SZ_C, SZ_N, SZ_C, SZ_C, SZ_C,
        (long)SZ_N * SZ_C, (long)SZ_N * SZ_C, (long)SZ_C * SZ_C);

    softmax_rows<<<SZ_B * SZ_C, 256>>>(s2_, SZ_C);

    // cav[b] = x[b] @ p2[b]  (NN, batch 16, K=1280)
    mma_gemm<false, false><<<dim3(10, 8, SZ_B), 256, SMEM>>>(
        x, s2_, cav_, SZ_C, SZ_C, SZ_C, SZ_C, SZ_C,
        (long)SZ_N * SZ_C, (long)SZ_C * SZ_C, (long)SZ_N * SZ_C);

    const long n4 = (long)SZ_BN * SZ_C / 4;
    epilogue_kernel<<<(unsigned)((n4 + 255) / 256), 256>>>(
        x, pav_, cav_, gamma, beta, out, n4);
}

// round 12
// speedup vs baseline: 3.8039x; 3.8039x over previous
#include <cuda_runtime.h>
#include <cuda_bf16.h>
#include <cstdint>

// Problem shape: B=16, N=1024, C=1280, d=160
#define SZ_B   16
#define SZ_N   1024
#define SZ_C   1280
#define SZ_D   160
#define SZ_BN  (SZ_B * SZ_N)

typedef __nv_bfloat16 bf16;

// ---------------------------------------------------------------------------
// Scratch (static __device__ globals) — ~815 MB
// ---------------------------------------------------------------------------
__device__ float g_k  [(size_t)SZ_BN * SZ_D];
__device__ float g_q  [(size_t)SZ_BN * SZ_D];
__device__ float g_v  [(size_t)SZ_BN * SZ_C];        // reused for cav
__device__ float g_s  [(size_t)SZ_B * SZ_N * SZ_N];
__device__ float g_s2 [(size_t)SZ_B * SZ_C * SZ_C];
__device__ float g_pav[(size_t)SZ_BN * SZ_C];

__device__ bf16 g_xh [(size_t)SZ_BN * SZ_C];
__device__ bf16 g_xl [(size_t)SZ_BN * SZ_C];
__device__ bf16 g_xth[(size_t)SZ_B * SZ_C * SZ_N];   // xT[b][c][n]
__device__ bf16 g_xtl[(size_t)SZ_B * SZ_C * SZ_N];
__device__ bf16 g_wkth[(size_t)SZ_D * SZ_C];
__device__ bf16 g_wktl[(size_t)SZ_D * SZ_C];
__device__ bf16 g_wqth[(size_t)SZ_D * SZ_C];
__device__ bf16 g_wqtl[(size_t)SZ_D * SZ_C];
__device__ bf16 g_wvth[(size_t)SZ_C * SZ_C];
__device__ bf16 g_wvtl[(size_t)SZ_C * SZ_C];
__device__ bf16 g_kh [(size_t)SZ_BN * SZ_D];
__device__ bf16 g_kl [(size_t)SZ_BN * SZ_D];
__device__ bf16 g_qh [(size_t)SZ_BN * SZ_D];
__device__ bf16 g_ql [(size_t)SZ_BN * SZ_D];
__device__ bf16 g_vth[(size_t)SZ_B * SZ_C * SZ_N];   // vT[b][c][n]
__device__ bf16 g_vtl[(size_t)SZ_B * SZ_C * SZ_N];
__device__ bf16 g_ph [(size_t)SZ_B * SZ_N * SZ_N];
__device__ bf16 g_pl [(size_t)SZ_B * SZ_N * SZ_N];
__device__ bf16 g_p2th[(size_t)SZ_B * SZ_C * SZ_C];  // p2T[b][e][c]
__device__ bf16 g_p2tl[(size_t)SZ_B * SZ_C * SZ_C];

// ---------------------------------------------------------------------------
// PTX helpers (base-target: ldmatrix sm_75+, bf16 mma sm_80+, cp.async sm_80+)
// ---------------------------------------------------------------------------
__device__ __forceinline__ uint32_t smem_u32(const void* p) {
    uint32_t a;
    asm("{ .reg .u64 t; cvta.to.shared.u64 t, %1; cvt.u32.u64 %0, t; }"
        : "=r"(a) : "l"(p));
    return a;
}
#define SWZ128(off) ((off) ^ (((off) >> 3) & 0x70))

__device__ __forceinline__ void ldsm4(uint32_t& a0, uint32_t& a1, uint32_t& a2,
                                      uint32_t& a3, uint32_t addr) {
    asm volatile("ldmatrix.sync.aligned.m8n8.x4.shared.b16 {%0,%1,%2,%3}, [%4];"
                 : "=r"(a0), "=r"(a1), "=r"(a2), "=r"(a3) : "r"(addr));
}
__device__ __forceinline__ void ldsm2(uint32_t& b0, uint32_t& b1, uint32_t addr) {
    asm volatile("ldmatrix.sync.aligned.m8n8.x2.shared.b16 {%0,%1}, [%2];"
                 : "=r"(b0), "=r"(b1) : "r"(addr));
}
__device__ __forceinline__ void mma16816(float* c, const uint32_t* a,
                                         const uint32_t* b) {
    asm volatile(
        "mma.sync.aligned.m16n8k16.row.col.f32.bf16.bf16.f32 "
        "{%0,%1,%2,%3}, {%4,%5,%6,%7}, {%8,%9}, {%0,%1,%2,%3};"
        : "+f"(c[0]), "+f"(c[1]), "+f"(c[2]), "+f"(c[3])
        : "r"(a[0]), "r"(a[1]), "r"(a[2]), "r"(a[3]), "r"(b[0]), "r"(b[1]));
}
__device__ __forceinline__ void cp16(uint32_t dst, const void* src, int sz) {
    asm volatile("cp.async.cg.shared.global [%0], [%1], 16, %2;"
                 :: "r"(dst), "l"(src), "r"(sz));
}
#define CP_COMMIT() asm volatile("cp.async.commit_group;" ::: "memory")

// ---------------------------------------------------------------------------
// Unified NT GEMM, bf16 hi/lo 3-term, cp.async 3-stage pipeline.
//   C[m][n] = sum_k A[m][k]*B[n][k]   (both operands k-contiguous, pre-split)
//   CTA tile 128x128, K-chunk 64 (row = 128 B, SW128). smem 3 x 64 KB.
// ---------------------------------------------------------------------------
#define T_BYTES 16384    // one 128x64 bf16 tile
#define STG     65536    // Ah+Al+Bh+Bl per stage
#define STAGES  3

__global__ __launch_bounds__(256, 1)
void gemm_hl(const bf16* __restrict__ Ah, const bf16* __restrict__ Al,
             const bf16* __restrict__ Bh, const bf16* __restrict__ Bl,
             float* __restrict__ C, int Ncols, int K,
             int lda, int ldb, int ldc, long sA, long sB, long sC)
{
    extern __shared__ char smem[];
    Ah += (long)blockIdx.z * sA;  Al += (long)blockIdx.z * sA;
    Bh += (long)blockIdx.z * sB;  Bl += (long)blockIdx.z * sB;
    C  += (long)blockIdx.z * sC;

    const int tid  = threadIdx.x;
    const int lane = tid & 31;
    const int wid  = tid >> 5;
    const int wm   = wid & 1;
    const int wn   = wid >> 1;
    const int m0   = blockIdx.y * 128;
    const int n0   = blockIdx.x * 128;

    const uint32_t sb = smem_u32(smem);
    const int nch = (K + 63) / 64;

    // stage one 128x64 tile via 16B cp.async granules (8 per row)
    auto stage_tile = [&](const bf16* src, int ld, uint32_t dstBase,
                          int base0, int rowsValid, int k0) {
        for (int g = tid; g < 1024; g += 256) {
            const int row = g >> 3, gc = g & 7;
            const uint32_t dst = dstBase + SWZ128((uint32_t)(row * 128 + gc * 16));
            const void* p = src + (long)(base0 + row) * ld + k0 + gc * 8;
            const int sz = (base0 + row < rowsValid && k0 + gc * 8 < K) ? 16 : 0;
            cp16(dst, p, sz);
        }
    };
    auto issue_stage = [&](int ch, int buf) {
        const int k0 = ch * 64;
        const uint32_t base = sb + buf * STG;
        stage_tile(Ah, lda, base,               m0, 1 << 30, k0);
        stage_tile(Al, lda, base + T_BYTES,     m0, 1 << 30, k0);
        stage_tile(Bh, ldb, base + 2 * T_BYTES, n0, Ncols,   k0);
        stage_tile(Bl, ldb, base + 3 * T_BYTES, n0, Ncols,   k0);
        CP_COMMIT();
    };

    float acc[4][4][4];
#pragma unroll
    for (int i = 0; i < 4; i++)
#pragma unroll
        for (int j = 0; j < 4; j++)
#pragma unroll
            for (int u = 0; u < 4; u++) acc[i][j][u] = 0.f;

    for (int st = 0; st < STAGES && st < nch; st++) issue_stage(st, st);

    const int r8 = lane & 7;
    const int bhalf = (lane >> 3) & 1;
    const int g2 = lane >> 3;

    for (int ch = 0; ch < nch; ch++) {
        int pend = nch - 1 - ch;
        if (pend > STAGES - 1) pend = STAGES - 1;
        if (pend == 0)      asm volatile("cp.async.wait_group 0;" ::: "memory");
        else if (pend == 1) asm volatile("cp.async.wait_group 1;" ::: "memory");
        else                asm volatile("cp.async.wait_group 2;" ::: "memory");
        __syncthreads();

        const uint32_t aBh = sb + (ch % STAGES) * STG;
        const uint32_t aBl = aBh + T_BYTES;
        const uint32_t bBh = aBh + 2 * T_BYTES;
        const uint32_t bBl = aBh + 3 * T_BYTES;

#pragma unroll
        for (int kt = 0; kt < 4; kt++) {
            uint32_t bh[4][2], bl[4][2];
#pragma unroll
            for (int nt = 0; nt < 4; nt++) {
                const int brow = wn * 32 + nt * 8 + r8;
                const uint32_t boff =
                    SWZ128((uint32_t)(brow * 128 + (2 * kt + bhalf) * 16));
                ldsm2(bh[nt][0], bh[nt][1], bBh + boff);
                ldsm2(bl[nt][0], bl[nt][1], bBl + boff);
            }
#pragma unroll
            for (int mt = 0; mt < 4; mt++) {
                const int arow = wm * 64 + mt * 16 + (g2 & 1) * 8 + r8;
                const uint32_t aoff =
                    SWZ128((uint32_t)(arow * 128 + (2 * kt + (g2 >> 1)) * 16));
                uint32_t ah[4], al[4];
                ldsm4(ah[0], ah[1], ah[2], ah[3], aBh + aoff);
                ldsm4(al[0], al[1], al[2], al[3], aBl + aoff);
#pragma unroll
                for (int nt = 0; nt < 4; nt++) {
                    mma16816(acc[mt][nt], ah, bh[nt]);
                    mma16816(acc[mt][nt], ah, bl[nt]);
                    mma16816(acc[mt][nt], al, bh[nt]);
                }
            }
        }
        __syncthreads();
        if (ch + STAGES < nch) issue_stage(ch + STAGES, ch % STAGES);
    }

#pragma unroll
    for (int mt = 0; mt < 4; mt++) {
#pragma unroll
        for (int nt = 0; nt < 4; nt++) {
            const int row0 = m0 + wm * 64 + mt * 16 + (lane >> 2);
            const int col  = n0 + wn * 32 + nt * 8 + (lane & 3) * 2;
            if (col < Ncols) {
                *reinterpret_cast<float2*>(C + (long)row0 * ldc + col) =
                    make_float2(acc[mt][nt][0], acc[mt][nt][1]);
                *reinterpret_cast<float2*>(C + (long)(row0 + 8) * ldc + col) =
                    make_float2(acc[mt][nt][2], acc[mt][nt][3]);
            }
        }
    }
}

// ---------------------------------------------------------------------------
// Elementwise fp32 -> bf16 hi/lo split (vectorized)
// ---------------------------------------------------------------------------
__global__ void conv_split(const float* __restrict__ in, bf16* __restrict__ h,
                           bf16* __restrict__ l, long n4)
{
    const long i = (long)blockIdx.x * 256 + threadIdx.x;
    if (i >= n4) return;
    const float4 v = reinterpret_cast<const float4*>(in)[i];
    const float vv[4] = {v.x, v.y, v.z, v.w};
    bf16 hh[4], ll[4];
#pragma unroll
    for (int u = 0; u < 4; u++) {
        hh[u] = __float2bfloat16(vv[u]);
        ll[u] = __float2bfloat16(vv[u] - __bfloat162float(hh[u]));
    }
    reinterpret_cast<uint2*>(h)[i] = *reinterpret_cast<uint2*>(hh);
    reinterpret_cast<uint2*>(l)[i] = *reinterpret_cast<uint2*>(ll);
}

// ---------------------------------------------------------------------------
// Batched transpose + split: in fp32 [R][Cc] -> outH/outL bf16 [Cc][R]
// ---------------------------------------------------------------------------
__global__ void transpose_split(const float* __restrict__ in,
                                bf16* __restrict__ outH, bf16* __restrict__ outL,
                                int R, int Cc, long sIn, long sOut)
{
    __shared__ float t[32][33];
    in   += (long)blockIdx.z * sIn;
    outH += (long)blockIdx.z * sOut;
    outL += (long)blockIdx.z * sOut;
    const int c0 = blockIdx.x * 32, r0 = blockIdx.y * 32;
    const int tx = threadIdx.x & 31, ty = threadIdx.x >> 5;

#pragma unroll
    for (int i = 0; i < 32; i += 8) {
        const int r = r0 + ty + i, c = c0 + tx;
        t[ty + i][tx] = (r < R && c < Cc) ? in[(long)r * Cc + c] : 0.f;
    }
    __syncthreads();
#pragma unroll
    for (int i = 0; i < 32; i += 8) {
        const int c = c0 + ty + i, r = r0 + tx;
        if (c < Cc && r < R) {
            const float v = t[tx][ty + i];
            const bf16 h = __float2bfloat16(v);
            outH[(long)c * R + r] = h;
            outL[(long)c * R + r] = __float2bfloat16(v - __bfloat162float(h));
        }
    }
}

// ---------------------------------------------------------------------------
// Row softmax, emitting bf16 hi/lo probabilities (input untouched)
// ---------------------------------------------------------------------------
__global__ void softmax_emit(const float* __restrict__ s, bf16* __restrict__ ph,
                             bf16* __restrict__ pl, int L)
{
    const float* p = s + (long)blockIdx.x * L;
    bf16* oh = ph + (long)blockIdx.x * L;
    bf16* ol = pl + (long)blockIdx.x * L;
    const int tid = threadIdx.x;
    __shared__ float red[8];

    float m = -3.402823466e38f;
    for (int i = tid; i < L; i += 256) m = fmaxf(m, p[i]);
#pragma unroll
    for (int o = 16; o; o >>= 1) m = fmaxf(m, __shfl_xor_sync(0xffffffffu, m, o));
    if ((tid & 31) == 0) red[tid >> 5] = m;
    __syncthreads();
    m = red[0];
#pragma unroll
    for (int w = 1; w < 8; w++) m = fmaxf(m, red[w]);

    float sum = 0.f;
    for (int i = tid; i < L; i += 256) sum += __expf(p[i] - m);
#pragma unroll
    for (int o = 16; o; o >>= 1) sum += __shfl_xor_sync(0xffffffffu, sum, o);
    __syncthreads();
    if ((tid & 31) == 0) red[tid >> 5] = sum;
    __syncthreads();
    sum = 0.f;
#pragma unroll
    for (int w = 0; w < 8; w++) sum += red[w];

    const float inv = 1.0f / sum;
    for (int i = tid; i < L; i += 256) {
        const float e = __expf(p[i] - m) * inv;
        const bf16 h = __float2bfloat16(e);
        oh[i] = h;
        ol[i] = __float2bfloat16(e - __bfloat162float(h));
    }
}

// In-place fp32 row softmax (for s2)
__global__ void softmax_rows(float* __restrict__ data, int L)
{
    float* p = data + (long)blockIdx.x * L;
    const int tid = threadIdx.x;
    __shared__ float red[8];

    float m = -3.402823466e38f;
    for (int i = tid; i < L; i += 256) m = fmaxf(m, p[i]);
#pragma unroll
    for (int o = 16; o; o >>= 1) m = fmaxf(m, __shfl_xor_sync(0xffffffffu, m, o));
    if ((tid & 31) == 0) red[tid >> 5] = m;
    __syncthreads();
    m = red[0];
#pragma unroll
    for (int w = 1; w < 8; w++) m = fmaxf(m, red[w]);

    float s = 0.f;
    for (int i = tid; i < L; i += 256) {
        const float e = __expf(p[i] - m);
        p[i] = e;
        s += e;
    }
#pragma unroll
    for (int o = 16; o; o >>= 1) s += __shfl_xor_sync(0xffffffffu, s, o);
    __syncthreads();
    if ((tid & 31) == 0) red[tid >> 5] = s;
    __syncthreads();
    s = 0.f;
#pragma unroll
    for (int w = 0; w < 8; w++) s += red[w];

    const float inv = 1.0f / s;
    for (int i = tid; i < L; i += 256) p[i] *= inv;
}

// ---------------------------------------------------------------------------
// Epilogue: out = gamma*pav + beta*cav + 2*x
// ---------------------------------------------------------------------------
__global__ void epilogue_kernel(const float* __restrict__ x,
                                const float* __restrict__ pav,
                                const float* __restrict__ cav,
                                const float* __restrict__ gamma,
                                const float* __restrict__ beta,
                                float* __restrict__ out, long n4)
{
    const long i = (long)blockIdx.x * blockDim.x + threadIdx.x;
    if (i >= n4) return;
    const float g = __ldg(gamma);
    const float bt = __ldg(beta);
    const float4 xp = reinterpret_cast<const float4*>(x)[i];
    const float4 pp = reinterpret_cast<const float4*>(pav)[i];
    const float4 cp = reinterpret_cast<const float4*>(cav)[i];
    float4 o;
    o.x = g * pp.x + bt * cp.x + 2.f * xp.x;
    o.y = g * pp.y + bt * cp.y + 2.f * xp.y;
    o.z = g * pp.z + bt * cp.z + 2.f * xp.z;
    o.w = g * pp.w + bt * cp.w + 2.f * xp.w;
    reinterpret_cast<float4*>(out)[i] = o;
}

// ---------------------------------------------------------------------------
// kernel_launch
// ---------------------------------------------------------------------------
extern "C" void kernel_launch(void* const* d_in, const int* in_sizes, int n_in,
                              void* d_out, int out_size)
{
    const float* x     = (const float*)d_in[0];
    const float* Wk    = (const float*)d_in[1];
    const float* Wq    = (const float*)d_in[2];
    const float* Wv    = (const float*)d_in[3];
    const float* gamma = (const float*)d_in[4];
    const float* beta  = (const float*)d_in[5];
    float* out = (float*)d_out;

    float *k_, *q_, *v_, *s_, *s2_, *pav_;
    bf16 *xh, *xl, *xth, *xtl, *wkth, *wktl, *wqth, *wqtl, *wvth, *wvtl;
    bf16 *kh, *kl, *qh, *ql, *vth, *vtl, *ph, *pl, *p2th, *p2tl;
    cudaGetSymbolAddress((void**)&k_,   g_k);
    cudaGetSymbolAddress((void**)&q_,   g_q);
    cudaGetSymbolAddress((void**)&v_,   g_v);
    cudaGetSymbolAddress((void**)&s_,   g_s);
    cudaGetSymbolAddress((void**)&s2_,  g_s2);
    cudaGetSymbolAddress((void**)&pav_, g_pav);
    cudaGetSymbolAddress((void**)&xh,   g_xh);
    cudaGetSymbolAddress((void**)&xl,   g_xl);
    cudaGetSymbolAddress((void**)&xth,  g_xth);
    cudaGetSymbolAddress((void**)&xtl,  g_xtl);
    cudaGetSymbolAddress((void**)&wkth, g_wkth);
    cudaGetSymbolAddress((void**)&wktl, g_wktl);
    cudaGetSymbolAddress((void**)&wqth, g_wqth);
    cudaGetSymbolAddress((void**)&wqtl, g_wqtl);
    cudaGetSymbolAddress((void**)&wvth, g_wvth);
    cudaGetSymbolAddress((void**)&wvtl, g_wvtl);
    cudaGetSymbolAddress((void**)&kh,   g_kh);
    cudaGetSymbolAddress((void**)&kl,   g_kl);
    cudaGetSymbolAddress((void**)&qh,   g_qh);
    cudaGetSymbolAddress((void**)&ql,   g_ql);
    cudaGetSymbolAddress((void**)&vth,  g_vth);
    cudaGetSymbolAddress((void**)&vtl,  g_vtl);
    cudaGetSymbolAddress((void**)&ph,   g_ph);
    cudaGetSymbolAddress((void**)&pl,   g_pl);
    cudaGetSymbolAddress((void**)&p2th, g_p2th);
    cudaGetSymbolAddress((void**)&p2tl, g_p2tl);
    float* cav_ = v_;   // v fp32 dead after vT conversion

    constexpr int SMEM = STAGES * STG;   // 196608 B
    cudaFuncSetAttribute((const void*)gemm_hl,
                         cudaFuncAttributeMaxDynamicSharedMemorySize, SMEM);

    // ---- operand preparation ----
    conv_split<<<(unsigned)(((long)SZ_BN * SZ_C / 4 + 255) / 256), 256>>>(
        x, xh, xl, (long)SZ_BN * SZ_C / 4);
    transpose_split<<<dim3(40, 32, SZ_B), 256>>>(
        x, xth, xtl, SZ_N, SZ_C, (long)SZ_N * SZ_C, (long)SZ_C * SZ_N);
    transpose_split<<<dim3(5, 40, 1), 256>>>(Wk, wkth, wktl, SZ_C, SZ_D, 0, 0);
    transpose_split<<<dim3(5, 40, 1), 256>>>(Wq, wqth, wqtl, SZ_C, SZ_D, 0, 0);
    transpose_split<<<dim3(40, 40, 1), 256>>>(Wv, wvth, wvtl, SZ_C, SZ_C, 0, 0);

    // ---- k, q, v projections ----
    gemm_hl<<<dim3(2, 128, 1), 256, SMEM>>>(
        xh, xl, wkth, wktl, k_, SZ_D, SZ_C, SZ_C, SZ_C, SZ_D, 0, 0, 0);
    gemm_hl<<<dim3(2, 128, 1), 256, SMEM>>>(
        xh, xl, wqth, wqtl, q_, SZ_D, SZ_C, SZ_C, SZ_C, SZ_D, 0, 0, 0);
    gemm_hl<<<dim3(10, 128, 1), 256, SMEM>>>(
        xh, xl, wvth, wvtl, v_, SZ_C, SZ_C, SZ_C, SZ_C, SZ_C, 0, 0, 0);

    conv_split<<<(unsigned)(((long)SZ_BN * SZ_D / 4 + 255) / 256), 256>>>(
        k_, kh, kl, (long)SZ_BN * SZ_D / 4);
    conv_split<<<(unsigned)(((long)SZ_BN * SZ_D / 4 + 255) / 256), 256>>>(
        q_, qh, ql, (long)SZ_BN * SZ_D / 4);
    transpose_split<<<dim3(40, 32, SZ_B), 256>>>(
        v_, vth, vtl, SZ_N, SZ_C, (long)SZ_N * SZ_C, (long)SZ_C * SZ_N);

    // ---- s = k @ q^T, softmax -> p hi/lo ----
    gemm_hl<<<dim3(8, 8, SZ_B), 256, SMEM>>>(
        kh, kl, qh, ql, s_, SZ_N, SZ_D, SZ_D, SZ_D, SZ_N,
        (long)SZ_N * SZ_D, (long)SZ_N * SZ_D, (long)SZ_N * SZ_N);
    softmax_emit<<<SZ_B * SZ_N, 256>>>(s_, ph, pl, SZ_N);

    // ---- pav = p @ v ----
    gemm_hl<<<dim3(10, 8, SZ_B), 256, SMEM>>>(
        ph, pl, vth, vtl, pav_, SZ_C, SZ_N, SZ_N, SZ_N, SZ_C,
        (long)SZ_N * SZ_N, (long)SZ_C * SZ_N, (long)SZ_N * SZ_C);

    // ---- s2 = x^T @ x, softmax, transpose -> p2T hi/lo ----
    gemm_hl<<<dim3(10, 10, SZ_B), 256, SMEM>>>(
        xth, xtl, xth, xtl, s2_, SZ_C, SZ_N, SZ_N, SZ_N, SZ_C,
        (long)SZ_C * SZ_N, (long)SZ_C * SZ_N, (long)SZ_C * SZ_C);
    softmax_rows<<<SZ_B * SZ_C, 256>>>(s2_, SZ_C);
    transpose_split<<<dim3(40, 40, SZ_B), 256>>>(
        s2_, p2th, p2tl, SZ_C, SZ_C, (long)SZ_C * SZ_C, (long)SZ_C * SZ_C);

    // ---- cav = x @ p2 ----
    gemm_hl<<<dim3(10, 8, SZ_B), 256, SMEM>>>(
        xh, xl, p2th, p2tl, cav_, SZ_C, SZ_C, SZ_C, SZ_C, SZ_C,
        (long)SZ_N * SZ_C, (long)SZ_C * SZ_C, (long)SZ_N * SZ_C);

    // ---- out = gamma*pav + beta*cav + 2*x ----
    const long n4 = (long)SZ_BN * SZ_C / 4;
    epilogue_kernel<<<(unsigned)((n4 + 255) / 256), 256>>>(
        x, pav_, cav_, gamma, beta, out, n4);
}

// round 13
// speedup vs baseline: 3.8664x; 1.0164x over previous
#include <cuda_runtime.h>
#include <cuda_bf16.h>
#include <cstdint>

// Problem shape: B=16, N=1024, C=1280, d=160
#define SZ_B   16
#define SZ_N   1024
#define SZ_C   1280
#define SZ_D   160
#define SZ_BN  (SZ_B * SZ_N)

typedef __nv_bfloat16 bf16;

// ---------------------------------------------------------------------------
// Scratch (static __device__ globals)
// ---------------------------------------------------------------------------
__device__ float g_s  [(size_t)SZ_B * SZ_N * SZ_N];    // 67 MB
__device__ float g_s2 [(size_t)SZ_B * SZ_C * SZ_C];    // 105 MB
__device__ float g_pav[(size_t)SZ_BN * SZ_C];          // 84 MB
__device__ float g_m2 [(size_t)SZ_B * SZ_C];           // col max of s2
__device__ float g_i2 [(size_t)SZ_B * SZ_C];           // col 1/sum of s2

__device__ bf16 g_xh  [(size_t)SZ_BN * SZ_C];
__device__ bf16 g_xl  [(size_t)SZ_BN * SZ_C];
__device__ bf16 g_xth [(size_t)SZ_B * SZ_C * SZ_N];    // xT[b][c][n]
__device__ bf16 g_xtl [(size_t)SZ_B * SZ_C * SZ_N];
__device__ bf16 g_wkth[(size_t)SZ_D * SZ_C];
__device__ bf16 g_wktl[(size_t)SZ_D * SZ_C];
__device__ bf16 g_wqth[(size_t)SZ_D * SZ_C];
__device__ bf16 g_wqtl[(size_t)SZ_D * SZ_C];
__device__ bf16 g_wvth[(size_t)SZ_C * SZ_C];
__device__ bf16 g_wvtl[(size_t)SZ_C * SZ_C];
__device__ bf16 g_kh  [(size_t)SZ_BN * SZ_D];
__device__ bf16 g_kl  [(size_t)SZ_BN * SZ_D];
__device__ bf16 g_qh  [(size_t)SZ_BN * SZ_D];
__device__ bf16 g_ql  [(size_t)SZ_BN * SZ_D];
__device__ bf16 g_vth [(size_t)SZ_C * SZ_BN];          // vT[c][b*N+n]
__device__ bf16 g_vtl [(size_t)SZ_C * SZ_BN];
__device__ bf16 g_ph  [(size_t)SZ_B * SZ_N * SZ_N];
__device__ bf16 g_pl  [(size_t)SZ_B * SZ_N * SZ_N];
__device__ bf16 g_p2th[(size_t)SZ_B * SZ_C * SZ_C];    // p2T[b][e][c]
__device__ bf16 g_p2tl[(size_t)SZ_B * SZ_C * SZ_C];

// ---------------------------------------------------------------------------
// PTX helpers (base-target: ldmatrix sm_75+, bf16 mma sm_80+, cp.async sm_80+)
// ---------------------------------------------------------------------------
__device__ __forceinline__ uint32_t smem_u32(const void* p) {
    uint32_t a;
    asm("{ .reg .u64 t; cvta.to.shared.u64 t, %1; cvt.u32.u64 %0, t; }"
        : "=r"(a) : "l"(p));
    return a;
}
#define SWZ128(off) ((off) ^ (((off) >> 3) & 0x70))

__device__ __forceinline__ void ldsm4(uint32_t& a0, uint32_t& a1, uint32_t& a2,
                                      uint32_t& a3, uint32_t addr) {
    asm volatile("ldmatrix.sync.aligned.m8n8.x4.shared.b16 {%0,%1,%2,%3}, [%4];"
                 : "=r"(a0), "=r"(a1), "=r"(a2), "=r"(a3) : "r"(addr));
}
__device__ __forceinline__ void mma16816(float* c, const uint32_t* a,
                                         const uint32_t* b) {
    asm volatile(
        "mma.sync.aligned.m16n8k16.row.col.f32.bf16.bf16.f32 "
        "{%0,%1,%2,%3}, {%4,%5,%6,%7}, {%8,%9}, {%0,%1,%2,%3};"
        : "+f"(c[0]), "+f"(c[1]), "+f"(c[2]), "+f"(c[3])
        : "r"(a[0]), "r"(a[1]), "r"(a[2]), "r"(a[3]), "r"(b[0]), "r"(b[1]));
}
__device__ __forceinline__ void cp16(uint32_t dst, const void* src, int sz) {
    asm volatile("cp.async.cg.shared.global [%0], [%1], 16, %2;"
                 :: "r"(dst), "l"(src), "r"(sz));
}
#define CP_COMMIT() asm volatile("cp.async.commit_group;" ::: "memory")

__device__ __forceinline__ uint32_t pack_hi(float a, float b) {
    __nv_bfloat162 h; h.x = __float2bfloat16(a); h.y = __float2bfloat16(b);
    return *reinterpret_cast<uint32_t*>(&h);
}
__device__ __forceinline__ uint32_t pack_lo(float a, float b) {
    const bf16 ha = __float2bfloat16(a), hb = __float2bfloat16(b);
    __nv_bfloat162 l;
    l.x = __float2bfloat16(a - __bfloat162float(ha));
    l.y = __float2bfloat16(b - __bfloat162float(hb));
    return *reinterpret_cast<uint32_t*>(&l);
}

// ---------------------------------------------------------------------------
// Unified NT GEMM, bf16 hi/lo 3-term, cp.async 3-stage pipeline.
//   acc[m][n] = sum_k A[m][k]*B[n][k]  (operands pre-split, k-contiguous)
//   OM=0: store fp32   OM=1: store bf16 hi/lo split   OM=2: fused final
//   (OM=2: out = gamma*pav + beta*acc + 2*x)
// ---------------------------------------------------------------------------
#define T_BYTES 16384
#define STG     65536
#define STAGES  3

template <int OM>
__global__ __launch_bounds__(256, 1)
void gemm_hl(const bf16* __restrict__ Ah, const bf16* __restrict__ Al,
             const bf16* __restrict__ Bh, const bf16* __restrict__ Bl,
             float* __restrict__ Cf, bf16* __restrict__ Ch, bf16* __restrict__ Cl,
             const float* __restrict__ Pv, const float* __restrict__ Xr,
             const float* __restrict__ gamma, const float* __restrict__ beta,
             int Ncols, int K, int lda, int ldb, int ldc,
             long sA, long sB, long sC)
{
    extern __shared__ char smem[];
    Ah += (long)blockIdx.z * sA;  Al += (long)blockIdx.z * sA;
    Bh += (long)blockIdx.z * sB;  Bl += (long)blockIdx.z * sB;
    if (OM == 0) Cf += (long)blockIdx.z * sC;
    if (OM == 1) { Ch += (long)blockIdx.z * sC; Cl += (long)blockIdx.z * sC; }
    if (OM == 2) { Cf += (long)blockIdx.z * sC; Pv += (long)blockIdx.z * sC;
                   Xr += (long)blockIdx.z * sC; }

    const int tid  = threadIdx.x;
    const int lane = tid & 31;
    const int wid  = tid >> 5;
    const int wm   = wid & 1;
    const int wn   = wid >> 1;
    const int m0   = blockIdx.y * 128;
    const int n0   = blockIdx.x * 128;

    const uint32_t sb = smem_u32(smem);
    const int nch = (K + 63) / 64;

    auto stage_tile = [&](const bf16* src, int ld, uint32_t dstBase,
                          int base0, int rowsValid, int k0) {
        for (int g = tid; g < 1024; g += 256) {
            const int row = g >> 3, gc = g & 7;
            const uint32_t dst = dstBase + SWZ128((uint32_t)(row * 128 + gc * 16));
            const void* p = src + (long)(base0 + row) * ld + k0 + gc * 8;
            const int sz = (base0 + row < rowsValid && k0 + gc * 8 < K) ? 16 : 0;
            cp16(dst, p, sz);
        }
    };
    auto issue_stage = [&](int ch, int buf) {
        const int k0 = ch * 64;
        const uint32_t base = sb + buf * STG;
        stage_tile(Ah, lda, base,               m0, 1 << 30, k0);
        stage_tile(Al, lda, base + T_BYTES,     m0, 1 << 30, k0);
        stage_tile(Bh, ldb, base + 2 * T_BYTES, n0, Ncols,   k0);
        stage_tile(Bl, ldb, base + 3 * T_BYTES, n0, Ncols,   k0);
        CP_COMMIT();
    };

    float acc[4][4][4];
#pragma unroll
    for (int i = 0; i < 4; i++)
#pragma unroll
        for (int j = 0; j < 4; j++)
#pragma unroll
            for (int u = 0; u < 4; u++) acc[i][j][u] = 0.f;

    for (int st = 0; st < STAGES && st < nch; st++) issue_stage(st, st);

    const int r8 = lane & 7;
    const int bhalf = (lane >> 3) & 1;        // k-half select (lanes grp of 8)
    const int bpair = (lane >> 4) & 1;        // nt-within-pair select
    const int g2 = lane >> 3;

    for (int ch = 0; ch < nch; ch++) {
        int pend = nch - 1 - ch;
        if (pend > STAGES - 1) pend = STAGES - 1;
        if (pend == 0)      asm volatile("cp.async.wait_group 0;" ::: "memory");
        else if (pend == 1) asm volatile("cp.async.wait_group 1;" ::: "memory");
        else                asm volatile("cp.async.wait_group 2;" ::: "memory");
        __syncthreads();

        const uint32_t aBh = sb + (ch % STAGES) * STG;
        const uint32_t aBl = aBh + T_BYTES;
        const uint32_t bBh = aBh + 2 * T_BYTES;
        const uint32_t bBl = aBh + 3 * T_BYTES;

#pragma unroll
        for (int kt = 0; kt < 4; kt++) {
            // B fragments: ldsm4 loads 2 nt-subtiles (both k-halves) at once
            uint32_t bh[4][2], bl[4][2];
#pragma unroll
            for (int ntp = 0; ntp < 2; ntp++) {
                const int brow = wn * 32 + (ntp * 2 + bpair) * 8 + r8;
                const uint32_t boff =
                    SWZ128((uint32_t)(brow * 128 + (2 * kt + bhalf) * 16));
                ldsm4(bh[ntp * 2][0], bh[ntp * 2][1],
                      bh[ntp * 2 + 1][0], bh[ntp * 2 + 1][1], bBh + boff);
                ldsm4(bl[ntp * 2][0], bl[ntp * 2][1],
                      bl[ntp * 2 + 1][0], bl[ntp * 2 + 1][1], bBl + boff);
            }
#pragma unroll
            for (int mt = 0; mt < 4; mt++) {
                const int arow = wm * 64 + mt * 16 + (g2 & 1) * 8 + r8;
                const uint32_t aoff =
                    SWZ128((uint32_t)(arow * 128 + (2 * kt + (g2 >> 1)) * 16));
                uint32_t ah[4], al[4];
                ldsm4(ah[0], ah[1], ah[2], ah[3], aBh + aoff);
                ldsm4(al[0], al[1], al[2], al[3], aBl + aoff);
#pragma unroll
                for (int nt = 0; nt < 4; nt++) {
                    mma16816(acc[mt][nt], ah, bh[nt]);
                    mma16816(acc[mt][nt], ah, bl[nt]);
                    mma16816(acc[mt][nt], al, bh[nt]);
                }
            }
        }
        __syncthreads();
        if (ch + STAGES < nch) issue_stage(ch + STAGES, ch % STAGES);
    }

    float gv = 0.f, bv = 0.f;
    if (OM == 2) { gv = __ldg(gamma); bv = __ldg(beta); }

#pragma unroll
    for (int mt = 0; mt < 4; mt++) {
#pragma unroll
        for (int nt = 0; nt < 4; nt++) {
            const int row0 = m0 + wm * 64 + mt * 16 + (lane >> 2);
            const int col  = n0 + wn * 32 + nt * 8 + (lane & 3) * 2;
            if (col >= Ncols) continue;
            const long o0 = (long)row0 * ldc + col;
            const long o1 = (long)(row0 + 8) * ldc + col;
            if (OM == 0) {
                *reinterpret_cast<float2*>(Cf + o0) =
                    make_float2(acc[mt][nt][0], acc[mt][nt][1]);
                *reinterpret_cast<float2*>(Cf + o1) =
                    make_float2(acc[mt][nt][2], acc[mt][nt][3]);
            } else if (OM == 1) {
                *reinterpret_cast<uint32_t*>(Ch + o0) =
                    pack_hi(acc[mt][nt][0], acc[mt][nt][1]);
                *reinterpret_cast<uint32_t*>(Cl + o0) =
                    pack_lo(acc[mt][nt][0], acc[mt][nt][1]);
                *reinterpret_cast<uint32_t*>(Ch + o1) =
                    pack_hi(acc[mt][nt][2], acc[mt][nt][3]);
                *reinterpret_cast<uint32_t*>(Cl + o1) =
                    pack_lo(acc[mt][nt][2], acc[mt][nt][3]);
            } else {
                const float2 p0 = *reinterpret_cast<const float2*>(Pv + o0);
                const float2 x0 = *reinterpret_cast<const float2*>(Xr + o0);
                const float2 p1 = *reinterpret_cast<const float2*>(Pv + o1);
                const float2 x1 = *reinterpret_cast<const float2*>(Xr + o1);
                *reinterpret_cast<float2*>(Cf + o0) = make_float2(
                    gv * p0.x + bv * acc[mt][nt][0] + 2.f * x0.x,
                    gv * p0.y + bv * acc[mt][nt][1] + 2.f * x0.y);
                *reinterpret_cast<float2*>(Cf + o1) = make_float2(
                    gv * p1.x + bv * acc[mt][nt][2] + 2.f * x1.x,
                    gv * p1.y + bv * acc[mt][nt][3] + 2.f * x1.y);
            }
        }
    }
}

// ---------------------------------------------------------------------------
// Elementwise fp32 -> bf16 hi/lo split
// ---------------------------------------------------------------------------
__global__ void conv_split(const float* __restrict__ in, bf16* __restrict__ h,
                           bf16* __restrict__ l, long n4)
{
    const long i = (long)blockIdx.x * 256 + threadIdx.x;
    if (i >= n4) return;
    const float4 v = reinterpret_cast<const float4*>(in)[i];
    uint2 hh, ll;
    hh.x = pack_hi(v.x, v.y); ll.x = pack_lo(v.x, v.y);
    hh.y = pack_hi(v.z, v.w); ll.y = pack_lo(v.z, v.w);
    reinterpret_cast<uint2*>(h)[i] = hh;
    reinterpret_cast<uint2*>(l)[i] = ll;
}

// ---------------------------------------------------------------------------
// Batched transpose + split: fp32 [R][Cc] -> bf16 [Cc][R] hi/lo
// ---------------------------------------------------------------------------
__global__ void transpose_split(const float* __restrict__ in,
                                bf16* __restrict__ outH, bf16* __restrict__ outL,
                                int R, int Cc, long sIn, long sOut)
{
    __shared__ float t[32][33];
    in   += (long)blockIdx.z * sIn;
    outH += (long)blockIdx.z * sOut;
    outL += (long)blockIdx.z * sOut;
    const int c0 = blockIdx.x * 32, r0 = blockIdx.y * 32;
    const int tx = threadIdx.x & 31, ty = threadIdx.x >> 5;

#pragma unroll
    for (int i = 0; i < 32; i += 8) {
        const int r = r0 + ty + i, c = c0 + tx;
        t[ty + i][tx] = (r < R && c < Cc) ? in[(long)r * Cc + c] : 0.f;
    }
    __syncthreads();
#pragma unroll
    for (int i = 0; i < 32; i += 8) {
        const int c = c0 + ty + i, r = r0 + tx;
        if (c < Cc && r < R) {
            const float v = t[tx][ty + i];
            const bf16 h = __float2bfloat16(v);
            outH[(long)c * R + r] = h;
            outL[(long)c * R + r] = __float2bfloat16(v - __bfloat162float(h));
        }
    }
}

// ---------------------------------------------------------------------------
// Row softmax emitting bf16 hi/lo (for p)
// ---------------------------------------------------------------------------
__global__ void softmax_emit(const float* __restrict__ s, bf16* __restrict__ ph,
                             bf16* __restrict__ pl, int L)
{
    const float* p = s + (long)blockIdx.x * L;
    bf16* oh = ph + (long)blockIdx.x * L;
    bf16* ol = pl + (long)blockIdx.x * L;
    const int tid = threadIdx.x;
    __shared__ float red[8];

    float m = -3.402823466e38f;
    for (int i = tid; i < L; i += 256) m = fmaxf(m, p[i]);
#pragma unroll
    for (int o = 16; o; o >>= 1) m = fmaxf(m, __shfl_xor_sync(0xffffffffu, m, o));
    if ((tid & 31) == 0) red[tid >> 5] = m;
    __syncthreads();
    m = red[0];
#pragma unroll
    for (int w = 1; w < 8; w++) m = fmaxf(m, red[w]);

    float sum = 0.f;
    for (int i = tid; i < L; i += 256) sum += __expf(p[i] - m);
#pragma unroll
    for (int o = 16; o; o >>= 1) sum += __shfl_xor_sync(0xffffffffu, sum, o);
    __syncthreads();
    if ((tid & 31) == 0) red[tid >> 5] = sum;
    __syncthreads();
    sum = 0.f;
#pragma unroll
    for (int w = 0; w < 8; w++) sum += red[w];

    const float inv = 1.0f / sum;
    for (int i = tid; i < L; i += 256) {
        const float e = __expf(p[i] - m) * inv;
        const bf16 h = __float2bfloat16(e);
        oh[i] = h;
        ol[i] = __float2bfloat16(e - __bfloat162float(h));
    }
}

// ---------------------------------------------------------------------------
// Per-row max + 1/sum stats for s2 (row c == column c by symmetry)
// ---------------------------------------------------------------------------
__global__ void rowstats(const float* __restrict__ s2, float* __restrict__ mArr,
                         float* __restrict__ iArr, int L)
{
    const float* p = s2 + (long)blockIdx.x * L;
    const int tid = threadIdx.x;
    __shared__ float red[8];

    float m = -3.402823466e38f;
    for (int i = tid; i < L; i += 256) m = fmaxf(m, p[i]);
#pragma unroll
    for (int o = 16; o; o >>= 1) m = fmaxf(m, __shfl_xor_sync(0xffffffffu, m, o));
    if ((tid & 31) == 0) red[tid >> 5] = m;
    __syncthreads();
    m = red[0];
#pragma unroll
    for (int w = 1; w < 8; w++) m = fmaxf(m, red[w]);

    float sum = 0.f;
    for (int i = tid; i < L; i += 256) sum += __expf(p[i] - m);
#pragma unroll
    for (int o = 16; o; o >>= 1) sum += __shfl_xor_sync(0xffffffffu, sum, o);
    __syncthreads();
    if ((tid & 31) == 0) red[tid >> 5] = sum;
    __syncthreads();
    sum = 0.f;
#pragma unroll
    for (int w = 0; w < 8; w++) sum += red[w];

    if (tid == 0) { mArr[blockIdx.x] = m; iArr[blockIdx.x] = 1.0f / sum; }
}

// p2T[b][e][c] = exp(s2[b][e][c] - m[b][c]) * inv[b][c]   (s2 symmetric)
__global__ void p2t_emit(const float* __restrict__ s2,
                         const float* __restrict__ mArr,
                         const float* __restrict__ iArr,
                         bf16* __restrict__ th, bf16* __restrict__ tl, int L)
{
    const long r = blockIdx.x;                 // global row b*C + e
    const long b = r / L;
    const float* p = s2 + r * L;
    const float* mb = mArr + b * L;
    const float* ib = iArr + b * L;
    bf16* oh = th + r * L;
    bf16* ol = tl + r * L;
    for (int c = threadIdx.x; c < L; c += 256) {
        const float v = __expf(p[c] - __ldg(mb + c)) * __ldg(ib + c);
        const bf16 h = __float2bfloat16(v);
        oh[c] = h;
        ol[c] = __float2bfloat16(v - __bfloat162float(h));
    }
}

// ---------------------------------------------------------------------------
// kernel_launch
// ---------------------------------------------------------------------------
extern "C" void kernel_launch(void* const* d_in, const int* in_sizes, int n_in,
                              void* d_out, int out_size)
{
    const float* x     = (const float*)d_in[0];
    const float* Wk    = (const float*)d_in[1];
    const float* Wq    = (const float*)d_in[2];
    const float* Wv    = (const float*)d_in[3];
    const float* gamma = (const float*)d_in[4];
    const float* beta  = (const float*)d_in[5];
    float* out = (float*)d_out;

    float *s_, *s2_, *pav_, *m2, *i2;
    bf16 *xh, *xl, *xth, *xtl, *wkth, *wktl, *wqth, *wqtl, *wvth, *wvtl;
    bf16 *kh, *kl, *qh, *ql, *vth, *vtl, *ph, *pl, *p2th, *p2tl;
    cudaGetSymbolAddress((void**)&s_,   g_s);
    cudaGetSymbolAddress((void**)&s2_,  g_s2);
    cudaGetSymbolAddress((void**)&pav_, g_pav);
    cudaGetSymbolAddress((void**)&m2,   g_m2);
    cudaGetSymbolAddress((void**)&i2,   g_i2);
    cudaGetSymbolAddress((void**)&xh,   g_xh);
    cudaGetSymbolAddress((void**)&xl,   g_xl);
    cudaGetSymbolAddress((void**)&xth,  g_xth);
    cudaGetSymbolAddress((void**)&xtl,  g_xtl);
    cudaGetSymbolAddress((void**)&wkth, g_wkth);
    cudaGetSymbolAddress((void**)&wktl, g_wktl);
    cudaGetSymbolAddress((void**)&wqth, g_wqth);
    cudaGetSymbolAddress((void**)&wqtl, g_wqtl);
    cudaGetSymbolAddress((void**)&wvth, g_wvth);
    cudaGetSymbolAddress((void**)&wvtl, g_wvtl);
    cudaGetSymbolAddress((void**)&kh,   g_kh);
    cudaGetSymbolAddress((void**)&kl,   g_kl);
    cudaGetSymbolAddress((void**)&qh,   g_qh);
    cudaGetSymbolAddress((void**)&ql,   g_ql);
    cudaGetSymbolAddress((void**)&vth,  g_vth);
    cudaGetSymbolAddress((void**)&vtl,  g_vtl);
    cudaGetSymbolAddress((void**)&ph,   g_ph);
    cudaGetSymbolAddress((void**)&pl,   g_pl);
    cudaGetSymbolAddress((void**)&p2th, g_p2th);
    cudaGetSymbolAddress((void**)&p2tl, g_p2tl);

    constexpr int SMEM = STAGES * STG;   // 196608
    cudaFuncSetAttribute((const void*)gemm_hl<0>,
                         cudaFuncAttributeMaxDynamicSharedMemorySize, SMEM);
    cudaFuncSetAttribute((const void*)gemm_hl<1>,
                         cudaFuncAttributeMaxDynamicSharedMemorySize, SMEM);
    cudaFuncSetAttribute((const void*)gemm_hl<2>,
                         cudaFuncAttributeMaxDynamicSharedMemorySize, SMEM);

    // ---- operand preparation ----
    conv_split<<<(unsigned)(((long)SZ_BN * SZ_C / 4 + 255) / 256), 256>>>(
        x, xh, xl, (long)SZ_BN * SZ_C / 4);
    transpose_split<<<dim3(40, 32, SZ_B), 256>>>(
        x, xth, xtl, SZ_N, SZ_C, (long)SZ_N * SZ_C, (long)SZ_C * SZ_N);
    transpose_split<<<dim3(5, 40, 1), 256>>>(Wk, wkth, wktl, SZ_C, SZ_D, 0, 0);
    transpose_split<<<dim3(5, 40, 1), 256>>>(Wq, wqth, wqtl, SZ_C, SZ_D, 0, 0);
    transpose_split<<<dim3(40, 40, 1), 256>>>(Wv, wvth, wvtl, SZ_C, SZ_C, 0, 0);

    // ---- k, q projections (direct bf16 hi/lo output) ----
    gemm_hl<1><<<dim3(2, 128, 1), 256, SMEM>>>(
        xh, xl, wkth, wktl, nullptr, kh, kl, nullptr, nullptr, nullptr, nullptr,
        SZ_D, SZ_C, SZ_C, SZ_C, SZ_D, 0, 0, 0);
    gemm_hl<1><<<dim3(2, 128, 1), 256, SMEM>>>(
        xh, xl, wqth, wqtl, nullptr, qh, ql, nullptr, nullptr, nullptr, nullptr,
        SZ_D, SZ_C, SZ_C, SZ_C, SZ_D, 0, 0, 0);

    // ---- vT[c][bn] = Wv^T @ x^T, computed directly transposed & split ----
    gemm_hl<1><<<dim3(128, 10, 1), 256, SMEM>>>(
        wvth, wvtl, xh, xl, nullptr, vth, vtl, nullptr, nullptr, nullptr, nullptr,
        SZ_BN, SZ_C, SZ_C, SZ_C, SZ_BN, 0, 0, 0);

    // ---- s = k @ q^T, softmax -> p hi/lo ----
    gemm_hl<0><<<dim3(8, 8, SZ_B), 256, SMEM>>>(
        kh, kl, qh, ql, s_, nullptr, nullptr, nullptr, nullptr, nullptr, nullptr,
        SZ_N, SZ_D, SZ_D, SZ_D, SZ_N,
        (long)SZ_N * SZ_D, (long)SZ_N * SZ_D, (long)SZ_N * SZ_N);
    softmax_emit<<<SZ_B * SZ_N, 256>>>(s_, ph, pl, SZ_N);

    // ---- pav = p @ v   (B = vT rows c, batch = column offset b*N) ----
    gemm_hl<0><<<dim3(10, 8, SZ_B), 256, SMEM>>>(
        ph, pl, vth, vtl, pav_, nullptr, nullptr, nullptr, nullptr, nullptr, nullptr,
        SZ_C, SZ_N, SZ_N, SZ_BN, SZ_C,
        (long)SZ_N * SZ_N, (long)SZ_N, (long)SZ_N * SZ_C);

    // ---- s2 = x^T @ x, column-stats softmax -> p2T hi/lo (symmetry) ----
    gemm_hl<0><<<dim3(10, 10, SZ_B), 256, SMEM>>>(
        xth, xtl, xth, xtl, s2_, nullptr, nullptr, nullptr, nullptr, nullptr, nullptr,
        SZ_C, SZ_N, SZ_N, SZ_N, SZ_C,
        (long)SZ_C * SZ_N, (long)SZ_C * SZ_N, (long)SZ_C * SZ_C);
    rowstats<<<SZ_B * SZ_C, 256>>>(s2_, m2, i2, SZ_C);
    p2t_emit<<<SZ_B * SZ_C, 256>>>(s2_, m2, i2, p2th, p2tl, SZ_C);

    // ---- final: out = gamma*pav + beta*(x @ p2) + 2*x  (fused) ----
    gemm_hl<2><<<dim3(10, 8, SZ_B), 256, SMEM>>>(
        xh, xl, p2th, p2tl, out, nullptr, nullptr, pav_, x, gamma, beta,
        SZ_C, SZ_C, SZ_C, SZ_C, SZ_C,
        (long)SZ_N * SZ_C, (long)SZ_C * SZ_C, (long)SZ_N * SZ_C);
}

// round 14
// speedup vs baseline: 4.3125x; 1.1154x over previous
#include <cuda_runtime.h>
#include <cuda_bf16.h>
#include <cstdint>

// Problem shape: B=16, N=1024, C=1280, d=160
#define SZ_B   16
#define SZ_N   1024
#define SZ_C   1280
#define SZ_D   160
#define SZ_BN  (SZ_B * SZ_N)

typedef __nv_bfloat16 bf16;

// ---------------------------------------------------------------------------
// Scratch (static __device__ globals)
// ---------------------------------------------------------------------------
__device__ float g_s  [(size_t)SZ_B * SZ_N * SZ_N];
__device__ float g_s2 [(size_t)SZ_B * SZ_C * SZ_C];
__device__ float g_pav[(size_t)SZ_BN * SZ_C];
__device__ float g_m2 [(size_t)SZ_B * SZ_C];
__device__ float g_i2 [(size_t)SZ_B * SZ_C];

__device__ bf16 g_xh  [(size_t)SZ_BN * SZ_C];
__device__ bf16 g_xl  [(size_t)SZ_BN * SZ_C];
__device__ bf16 g_xth [(size_t)SZ_B * SZ_C * SZ_N];
__device__ bf16 g_xtl [(size_t)SZ_B * SZ_C * SZ_N];
__device__ bf16 g_wkqth[(size_t)2 * SZ_D * SZ_C];     // [Wk^T ; Wq^T] rows 0..319
__device__ bf16 g_wkqtl[(size_t)2 * SZ_D * SZ_C];
__device__ bf16 g_wvth[(size_t)SZ_C * SZ_C];
__device__ bf16 g_wvtl[(size_t)SZ_C * SZ_C];
__device__ bf16 g_kqh [(size_t)SZ_BN * 2 * SZ_D];     // kq[bn][320]
__device__ bf16 g_kql [(size_t)SZ_BN * 2 * SZ_D];
__device__ bf16 g_vth [(size_t)SZ_C * SZ_BN];
__device__ bf16 g_vtl [(size_t)SZ_C * SZ_BN];
__device__ bf16 g_ph  [(size_t)SZ_B * SZ_N * SZ_N];
__device__ bf16 g_pl  [(size_t)SZ_B * SZ_N * SZ_N];
__device__ bf16 g_p2th[(size_t)SZ_B * SZ_C * SZ_C];
__device__ bf16 g_p2tl[(size_t)SZ_B * SZ_C * SZ_C];

// ---------------------------------------------------------------------------
// PTX helpers
// ---------------------------------------------------------------------------
__device__ __forceinline__ uint32_t smem_u32(const void* p) {
    uint32_t a;
    asm("{ .reg .u64 t; cvta.to.shared.u64 t, %1; cvt.u32.u64 %0, t; }"
        : "=r"(a) : "l"(p));
    return a;
}
#define SWZ128(off) ((off) ^ (((off) >> 3) & 0x70))

__device__ __forceinline__ void ldsm4(uint32_t& a0, uint32_t& a1, uint32_t& a2,
                                      uint32_t& a3, uint32_t addr) {
    asm volatile("ldmatrix.sync.aligned.m8n8.x4.shared.b16 {%0,%1,%2,%3}, [%4];"
                 : "=r"(a0), "=r"(a1), "=r"(a2), "=r"(a3) : "r"(addr));
}
__device__ __forceinline__ void mma16816(float* c, const uint32_t* a,
                                         const uint32_t* b) {
    asm volatile(
        "mma.sync.aligned.m16n8k16.row.col.f32.bf16.bf16.f32 "
        "{%0,%1,%2,%3}, {%4,%5,%6,%7}, {%8,%9}, {%0,%1,%2,%3};"
        : "+f"(c[0]), "+f"(c[1]), "+f"(c[2]), "+f"(c[3])
        : "r"(a[0]), "r"(a[1]), "r"(a[2]), "r"(a[3]), "r"(b[0]), "r"(b[1]));
}
__device__ __forceinline__ void cp16(uint32_t dst, const void* src, int sz) {
    asm volatile("cp.async.cg.shared.global [%0], [%1], 16, %2;"
                 :: "r"(dst), "l"(src), "r"(sz));
}
#define CP_COMMIT() asm volatile("cp.async.commit_group;" ::: "memory")

__device__ __forceinline__ uint32_t pack_hi(float a, float b) {
    __nv_bfloat162 h; h.x = __float2bfloat16(a); h.y = __float2bfloat16(b);
    return *reinterpret_cast<uint32_t*>(&h);
}
__device__ __forceinline__ uint32_t pack_lo(float a, float b) {
    const bf16 ha = __float2bfloat16(a), hb = __float2bfloat16(b);
    __nv_bfloat162 l;
    l.x = __float2bfloat16(a - __bfloat162float(ha));
    l.y = __float2bfloat16(b - __bfloat162float(hb));
    return *reinterpret_cast<uint32_t*>(&l);
}

// ---------------------------------------------------------------------------
// Unified NT GEMM, bf16 hi/lo 3-term, cp.async 3-stage pipeline.
//   OM=0: fp32 out   OM=1: bf16 hi/lo out   OM=2: fused final epilogue
//   SYM : triangular grid (blockIdx.x in [0,55)) + mirrored transposed store
// ---------------------------------------------------------------------------
#define T_BYTES 16384
#define STG     65536
#define STAGES  3

template <int OM, bool SYM>
__global__ __launch_bounds__(256, 1)
void gemm_hl(const bf16* __restrict__ Ah, const bf16* __restrict__ Al,
             const bf16* __restrict__ Bh, const bf16* __restrict__ Bl,
             float* __restrict__ Cf, bf16* __restrict__ Ch, bf16* __restrict__ Cl,
             const float* __restrict__ Pv, const float* __restrict__ Xr,
             const float* __restrict__ gamma, const float* __restrict__ beta,
             int Ncols, int K, int lda, int ldb, int ldc,
             long sA, long sB, long sC)
{
    extern __shared__ char smem[];
    Ah += (long)blockIdx.z * sA;  Al += (long)blockIdx.z * sA;
    Bh += (long)blockIdx.z * sB;  Bl += (long)blockIdx.z * sB;
    if (OM == 0) Cf += (long)blockIdx.z * sC;
    if (OM == 1) { Ch += (long)blockIdx.z * sC; Cl += (long)blockIdx.z * sC; }
    if (OM == 2) { Cf += (long)blockIdx.z * sC; Pv += (long)blockIdx.z * sC;
                   Xr += (long)blockIdx.z * sC; }

    const int tid  = threadIdx.x;
    const int lane = tid & 31;
    const int wid  = tid >> 5;
    const int wm   = wid & 1;
    const int wn   = wid >> 1;

    int bx, by;
    if (SYM) {                       // lower triangle incl. diagonal (bx <= by)
        int t = blockIdx.x, b = 0;
        while ((b + 1) * (b + 2) / 2 <= t) b++;
        by = b; bx = t - b * (b + 1) / 2;
    } else { bx = blockIdx.x; by = blockIdx.y; }
    const int m0 = by * 128;
    const int n0 = bx * 128;

    const uint32_t sb = smem_u32(smem);
    const int nch = (K + 63) / 64;

    auto stage_tile = [&](const bf16* src, int ld, uint32_t dstBase,
                          int base0, int rowsValid, int k0) {
        for (int g = tid; g < 1024; g += 256) {
            const int row = g >> 3, gc = g & 7;
            const uint32_t dst = dstBase + SWZ128((uint32_t)(row * 128 + gc * 16));
            const void* p = src + (long)(base0 + row) * ld + k0 + gc * 8;
            const int sz = (base0 + row < rowsValid && k0 + gc * 8 < K) ? 16 : 0;
            cp16(dst, p, sz);
        }
    };
    auto issue_stage = [&](int ch, int buf) {
        const int k0 = ch * 64;
        const uint32_t base = sb + buf * STG;
        stage_tile(Ah, lda, base,               m0, 1 << 30, k0);
        stage_tile(Al, lda, base + T_BYTES,     m0, 1 << 30, k0);
        stage_tile(Bh, ldb, base + 2 * T_BYTES, n0, Ncols,   k0);
        stage_tile(Bl, ldb, base + 3 * T_BYTES, n0, Ncols,   k0);
        CP_COMMIT();
    };

    float acc[4][4][4];
#pragma unroll
    for (int i = 0; i < 4; i++)
#pragma unroll
        for (int j = 0; j < 4; j++)
#pragma unroll
            for (int u = 0; u < 4; u++) acc[i][j][u] = 0.f;

    for (int st = 0; st < STAGES && st < nch; st++) issue_stage(st, st);

    const int r8 = lane & 7;
    const int bhalf = (lane >> 3) & 1;
    const int bpair = (lane >> 4) & 1;
    const int g2 = lane >> 3;

    for (int ch = 0; ch < nch; ch++) {
        int pend = nch - 1 - ch;
        if (pend > STAGES - 1) pend = STAGES - 1;
        if (pend == 0)      asm volatile("cp.async.wait_group 0;" ::: "memory");
        else if (pend == 1) asm volatile("cp.async.wait_group 1;" ::: "memory");
        else                asm volatile("cp.async.wait_group 2;" ::: "memory");
        __syncthreads();

        const uint32_t aBh = sb + (ch % STAGES) * STG;
        const uint32_t aBl = aBh + T_BYTES;
        const uint32_t bBh = aBh + 2 * T_BYTES;
        const uint32_t bBl = aBh + 3 * T_BYTES;

#pragma unroll
        for (int kt = 0; kt < 4; kt++) {
            uint32_t bh[4][2], bl[4][2];
#pragma unroll
            for (int ntp = 0; ntp < 2; ntp++) {
                const int brow = wn * 32 + (ntp * 2 + bpair) * 8 + r8;
                const uint32_t boff =
                    SWZ128((uint32_t)(brow * 128 + (2 * kt + bhalf) * 16));
                ldsm4(bh[ntp * 2][0], bh[ntp * 2][1],
                      bh[ntp * 2 + 1][0], bh[ntp * 2 + 1][1], bBh + boff);
                ldsm4(bl[ntp * 2][0], bl[ntp * 2][1],
                      bl[ntp * 2 + 1][0], bl[ntp * 2 + 1][1], bBl + boff);
            }
#pragma unroll
            for (int mt = 0; mt < 4; mt++) {
                const int arow = wm * 64 + mt * 16 + (g2 & 1) * 8 + r8;
                const uint32_t aoff =
                    SWZ128((uint32_t)(arow * 128 + (2 * kt + (g2 >> 1)) * 16));
                uint32_t ah[4], al[4];
                ldsm4(ah[0], ah[1], ah[2], ah[3], aBh + aoff);
                ldsm4(al[0], al[1], al[2], al[3], aBl + aoff);
#pragma unroll
                for (int nt = 0; nt < 4; nt++) {
                    mma16816(acc[mt][nt], ah, bh[nt]);
                    mma16816(acc[mt][nt], ah, bl[nt]);
                    mma16816(acc[mt][nt], al, bh[nt]);
                }
            }
        }
        __syncthreads();
        if (ch + STAGES < nch) issue_stage(ch + STAGES, ch % STAGES);
    }

    float gv = 0.f, bv = 0.f;
    if (OM == 2) { gv = __ldg(gamma); bv = __ldg(beta); }

#pragma unroll
    for (int mt = 0; mt < 4; mt++) {
#pragma unroll
        for (int nt = 0; nt < 4; nt++) {
            const int row0 = m0 + wm * 64 + mt * 16 + (lane >> 2);
            const int col  = n0 + wn * 32 + nt * 8 + (lane & 3) * 2;
            if (col >= Ncols) continue;
            const long o0 = (long)row0 * ldc + col;
            const long o1 = (long)(row0 + 8) * ldc + col;
            if (OM == 0) {
                *reinterpret_cast<float2*>(Cf + o0) =
                    make_float2(acc[mt][nt][0], acc[mt][nt][1]);
                *reinterpret_cast<float2*>(Cf + o1) =
                    make_float2(acc[mt][nt][2], acc[mt][nt][3]);
            } else if (OM == 1) {
                *reinterpret_cast<uint32_t*>(Ch + o0) =
                    pack_hi(acc[mt][nt][0], acc[mt][nt][1]);
                *reinterpret_cast<uint32_t*>(Cl + o0) =
                    pack_lo(acc[mt][nt][0], acc[mt][nt][1]);
                *reinterpret_cast<uint32_t*>(Ch + o1) =
                    pack_hi(acc[mt][nt][2], acc[mt][nt][3]);
                *reinterpret_cast<uint32_t*>(Cl + o1) =
                    pack_lo(acc[mt][nt][2], acc[mt][nt][3]);
            } else {
                const float2 p0 = *reinterpret_cast<const float2*>(Pv + o0);
                const float2 x0 = *reinterpret_cast<const float2*>(Xr + o0);
                const float2 p1 = *reinterpret_cast<const float2*>(Pv + o1);
                const float2 x1 = *reinterpret_cast<const float2*>(Xr + o1);
                *reinterpret_cast<float2*>(Cf + o0) = make_float2(
                    gv * p0.x + bv * acc[mt][nt][0] + 2.f * x0.x,
                    gv * p0.y + bv * acc[mt][nt][1] + 2.f * x0.y);
                *reinterpret_cast<float2*>(Cf + o1) = make_float2(
                    gv * p1.x + bv * acc[mt][nt][2] + 2.f * x1.x,
                    gv * p1.y + bv * acc[mt][nt][3] + 2.f * x1.y);
            }
        }
    }

    // Mirror store for symmetric output: C[n0+j][m0+i] = acc(i, j)
    if (SYM && bx != by) {
        __syncthreads();                       // stage buffers now reusable
        float* T = reinterpret_cast<float*>(smem);   // 128x128 fp32 = 64 KB
#pragma unroll
        for (int mt = 0; mt < 4; mt++) {
#pragma unroll
            for (int nt = 0; nt < 4; nt++) {
                const int r0 = wm * 64 + mt * 16 + (lane >> 2);
                const int c  = wn * 32 + nt * 8 + (lane & 3) * 2;
                T[(c)     * 128 + r0]     = acc[mt][nt][0];
                T[(c + 1) * 128 + r0]     = acc[mt][nt][1];
                T[(c)     * 128 + r0 + 8] = acc[mt][nt][2];
                T[(c + 1) * 128 + r0 + 8] = acc[mt][nt][3];
            }
        }
        __syncthreads();
        for (int idx = tid; idx < 128 * 32; idx += 256) {
            const int row = idx >> 5, c4 = idx & 31;
            const float4 v = reinterpret_cast<const float4*>(T + row * 128)[c4];
            *reinterpret_cast<float4*>(Cf + (long)(n0 + row) * ldc + m0 + c4 * 4) = v;
        }
    }
}

// ---------------------------------------------------------------------------
// Elementwise fp32 -> bf16 hi/lo split
// ---------------------------------------------------------------------------
__global__ void conv_split(const float* __restrict__ in, bf16* __restrict__ h,
                           bf16* __restrict__ l, long n4)
{
    const long i = (long)blockIdx.x * 256 + threadIdx.x;
    if (i >= n4) return;
    const float4 v = reinterpret_cast<const float4*>(in)[i];
    uint2 hh, ll;
    hh.x = pack_hi(v.x, v.y); ll.x = pack_lo(v.x, v.y);
    hh.y = pack_hi(v.z, v.w); ll.y = pack_lo(v.z, v.w);
    reinterpret_cast<uint2*>(h)[i] = hh;
    reinterpret_cast<uint2*>(l)[i] = ll;
}

// ---------------------------------------------------------------------------
// Batched transpose + split: fp32 [R][Cc] -> bf16 [Cc][R] hi/lo
// ---------------------------------------------------------------------------
__global__ void transpose_split(const float* __restrict__ in,
                                bf16* __restrict__ outH, bf16* __restrict__ outL,
                                int R, int Cc, long sIn, long sOut)
{
    __shared__ float t[32][33];
    in   += (long)blockIdx.z * sIn;
    outH += (long)blockIdx.z * sOut;
    outL += (long)blockIdx.z * sOut;
    const int c0 = blockIdx.x * 32, r0 = blockIdx.y * 32;
    const int tx = threadIdx.x & 31, ty = threadIdx.x >> 5;

#pragma unroll
    for (int i = 0; i < 32; i += 8) {
        const int r = r0 + ty + i, c = c0 + tx;
        t[ty + i][tx] = (r < R && c < Cc) ? in[(long)r * Cc + c] : 0.f;
    }
    __syncthreads();
#pragma unroll
    for (int i = 0; i < 32; i += 8) {
        const int c = c0 + ty + i, r = r0 + tx;
        if (c < Cc && r < R) {
            const float v = t[tx][ty + i];
            const bf16 h = __float2bfloat16(v);
            outH[(long)c * R + r] = h;
            outL[(long)c * R + r] = __float2bfloat16(v - __bfloat162float(h));
        }
    }
}

// ---------------------------------------------------------------------------
// Row softmax emitting bf16 hi/lo (for p)
// ---------------------------------------------------------------------------
__global__ void softmax_emit(const float* __restrict__ s, bf16* __restrict__ ph,
                             bf16* __restrict__ pl, int L)
{
    const float* p = s + (long)blockIdx.x * L;
    bf16* oh = ph + (long)blockIdx.x * L;
    bf16* ol = pl + (long)blockIdx.x * L;
    const int tid = threadIdx.x;
    __shared__ float red[8];

    float m = -3.402823466e38f;
    for (int i = tid; i < L; i += 256) m = fmaxf(m, p[i]);
#pragma unroll
    for (int o = 16; o; o >>= 1) m = fmaxf(m, __shfl_xor_sync(0xffffffffu, m, o));
    if ((tid & 31) == 0) red[tid >> 5] = m;
    __syncthreads();
    m = red[0];
#pragma unroll
    for (int w = 1; w < 8; w++) m = fmaxf(m, red[w]);

    float sum = 0.f;
    for (int i = tid; i < L; i += 256) sum += __expf(p[i] - m);
#pragma unroll
    for (int o = 16; o; o >>= 1) sum += __shfl_xor_sync(0xffffffffu, sum, o);
    __syncthreads();
    if ((tid & 31) == 0) red[tid >> 5] = sum;
    __syncthreads();
    sum = 0.f;
#pragma unroll
    for (int w = 0; w < 8; w++) sum += red[w];

    const float inv = 1.0f / sum;
    for (int i = tid; i < L; i += 256) {
        const float e = __expf(p[i] - m) * inv;
        const bf16 h = __float2bfloat16(e);
        oh[i] = h;
        ol[i] = __float2bfloat16(e - __bfloat162float(h));
    }
}

// ---------------------------------------------------------------------------
// Per-row stats for s2 (row c == column c by symmetry)
// ---------------------------------------------------------------------------
__global__ void rowstats(const float* __restrict__ s2, float* __restrict__ mArr,
                         float* __restrict__ iArr, int L)
{
    const float* p = s2 + (long)blockIdx.x * L;
    const int tid = threadIdx.x;
    __shared__ float red[8];

    float m = -3.402823466e38f;
    for (int i = tid; i < L; i += 256) m = fmaxf(m, p[i]);
#pragma unroll
    for (int o = 16; o; o >>= 1) m = fmaxf(m, __shfl_xor_sync(0xffffffffu, m, o));
    if ((tid & 31) == 0) red[tid >> 5] = m;
    __syncthreads();
    m = red[0];
#pragma unroll
    for (int w = 1; w < 8; w++) m = fmaxf(m, red[w]);

    float sum = 0.f;
    for (int i = tid; i < L; i += 256) sum += __expf(p[i] - m);
#pragma unroll
    for (int o = 16; o; o >>= 1) sum += __shfl_xor_sync(0xffffffffu, sum, o);
    __syncthreads();
    if ((tid & 31) == 0) red[tid >> 5] = sum;
    __syncthreads();
    sum = 0.f;
#pragma unroll
    for (int w = 0; w < 8; w++) sum += red[w];

    if (tid == 0) { mArr[blockIdx.x] = m; iArr[blockIdx.x] = 1.0f / sum; }
}

// p2T[b][e][c] = exp(s2[b][e][c] - m[b][c]) * inv[b][c]
__global__ void p2t_emit(const float* __restrict__ s2,
                         const float* __restrict__ mArr,
                         const float* __restrict__ iArr,
                         bf16* __restrict__ th, bf16* __restrict__ tl, int L)
{
    const long r = blockIdx.x;
    const long b = r / L;
    const float* p = s2 + r * L;
    const float* mb = mArr + b * L;
    const float* ib = iArr + b * L;
    bf16* oh = th + r * L;
    bf16* ol = tl + r * L;
    for (int c = threadIdx.x; c < L; c += 256) {
        const float v = __expf(p[c] - __ldg(mb + c)) * __ldg(ib + c);
        const bf16 h = __float2bfloat16(v);
        oh[c] = h;
        ol[c] = __float2bfloat16(v - __bfloat162float(h));
    }
}

// ---------------------------------------------------------------------------
// kernel_launch
// ---------------------------------------------------------------------------
extern "C" void kernel_launch(void* const* d_in, const int* in_sizes, int n_in,
                              void* d_out, int out_size)
{
    const float* x     = (const float*)d_in[0];
    const float* Wk    = (const float*)d_in[1];
    const float* Wq    = (const float*)d_in[2];
    const float* Wv    = (const float*)d_in[3];
    const float* gamma = (const float*)d_in[4];
    const float* beta  = (const float*)d_in[5];
    float* out = (float*)d_out;

    float *s_, *s2_, *pav_, *m2, *i2;
    bf16 *xh, *xl, *xth, *xtl, *wkqth, *wkqtl, *wvth, *wvtl;
    bf16 *kqh, *kql, *vth, *vtl, *ph, *pl, *p2th, *p2tl;
    cudaGetSymbolAddress((void**)&s_,    g_s);
    cudaGetSymbolAddress((void**)&s2_,   g_s2);
    cudaGetSymbolAddress((void**)&pav_,  g_pav);
    cudaGetSymbolAddress((void**)&m2,    g_m2);
    cudaGetSymbolAddress((void**)&i2,    g_i2);
    cudaGetSymbolAddress((void**)&xh,    g_xh);
    cudaGetSymbolAddress((void**)&xl,    g_xl);
    cudaGetSymbolAddress((void**)&xth,   g_xth);
    cudaGetSymbolAddress((void**)&xtl,   g_xtl);
    cudaGetSymbolAddress((void**)&wkqth, g_wkqth);
    cudaGetSymbolAddress((void**)&wkqtl, g_wkqtl);
    cudaGetSymbolAddress((void**)&wvth,  g_wvth);
    cudaGetSymbolAddress((void**)&wvtl,  g_wvtl);
    cudaGetSymbolAddress((void**)&kqh,   g_kqh);
    cudaGetSymbolAddress((void**)&kql,   g_kql);
    cudaGetSymbolAddress((void**)&vth,   g_vth);
    cudaGetSymbolAddress((void**)&vtl,   g_vtl);
    cudaGetSymbolAddress((void**)&ph,    g_ph);
    cudaGetSymbolAddress((void**)&pl,    g_pl);
    cudaGetSymbolAddress((void**)&p2th,  g_p2th);
    cudaGetSymbolAddress((void**)&p2tl,  g_p2tl);

    constexpr int SMEM = STAGES * STG;
    cudaFuncSetAttribute((const void*)gemm_hl<0, false>,
                         cudaFuncAttributeMaxDynamicSharedMemorySize, SMEM);
    cudaFuncSetAttribute((const void*)gemm_hl<0, true>,
                         cudaFuncAttributeMaxDynamicSharedMemorySize, SMEM);
    cudaFuncSetAttribute((const void*)gemm_hl<1, false>,
                         cudaFuncAttributeMaxDynamicSharedMemorySize, SMEM);
    cudaFuncSetAttribute((const void*)gemm_hl<2, false>,
                         cudaFuncAttributeMaxDynamicSharedMemorySize, SMEM);

    // ---- operand preparation ----
    conv_split<<<(unsigned)(((long)SZ_BN * SZ_C / 4 + 255) / 256), 256>>>(
        x, xh, xl, (long)SZ_BN * SZ_C / 4);
    transpose_split<<<dim3(40, 32, SZ_B), 256>>>(
        x, xth, xtl, SZ_N, SZ_C, (long)SZ_N * SZ_C, (long)SZ_C * SZ_N);
    transpose_split<<<dim3(5, 40, 1), 256>>>(Wk, wkqth, wkqtl, SZ_C, SZ_D, 0, 0);
    transpose_split<<<dim3(5, 40, 1), 256>>>(
        Wq, wkqth + (size_t)SZ_D * SZ_C, wkqtl + (size_t)SZ_D * SZ_C,
        SZ_C, SZ_D, 0, 0);
    transpose_split<<<dim3(40, 40, 1), 256>>>(Wv, wvth, wvtl, SZ_C, SZ_C, 0, 0);

    // ---- fused kq projection: kq[bn][320] ----
    gemm_hl<1, false><<<dim3(3, 128, 1), 256, SMEM>>>(
        xh, xl, wkqth, wkqtl, nullptr, kqh, kql, nullptr, nullptr, nullptr, nullptr,
        2 * SZ_D, SZ_C, SZ_C, SZ_C, 2 * SZ_D, 0, 0, 0);

    // ---- vT[c][bn] = Wv^T @ x^T  (direct transposed split output) ----
    gemm_hl<1, false><<<dim3(128, 10, 1), 256, SMEM>>>(
        wvth, wvtl, xh, xl, nullptr, vth, vtl, nullptr, nullptr, nullptr, nullptr,
        SZ_BN, SZ_C, SZ_C, SZ_C, SZ_BN, 0, 0, 0);

    // ---- s = k @ q^T (k rows at offset 0, q rows at offset 160; ld 320) ----
    gemm_hl<0, false><<<dim3(8, 8, SZ_B), 256, SMEM>>>(
        kqh, kql, kqh + SZ_D, kql + SZ_D, s_, nullptr, nullptr,
        nullptr, nullptr, nullptr, nullptr,
        SZ_N, SZ_D, 2 * SZ_D, 2 * SZ_D, SZ_N,
        (long)SZ_N * 2 * SZ_D, (long)SZ_N * 2 * SZ_D, (long)SZ_N * SZ_N);
    softmax_emit<<<SZ_B * SZ_N, 256>>>(s_, ph, pl, SZ_N);

    // ---- pav = p @ v ----
    gemm_hl<0, false><<<dim3(10, 8, SZ_B), 256, SMEM>>>(
        ph, pl, vth, vtl, pav_, nullptr, nullptr, nullptr, nullptr, nullptr, nullptr,
        SZ_C, SZ_N, SZ_N, SZ_BN, SZ_C,
        (long)SZ_N * SZ_N, (long)SZ_N, (long)SZ_N * SZ_C);

    // ---- s2 = x^T @ x, triangular grid (55 blocks) + mirror ----
    gemm_hl<0, true><<<dim3(55, 1, SZ_B), 256, SMEM>>>(
        xth, xtl, xth, xtl, s2_, nullptr, nullptr, nullptr, nullptr, nullptr, nullptr,
        SZ_C, SZ_N, SZ_N, SZ_N, SZ_C,
        (long)SZ_C * SZ_N, (long)SZ_C * SZ_N, (long)SZ_C * SZ_C);
    rowstats<<<SZ_B * SZ_C, 256>>>(s2_, m2, i2, SZ_C);
    p2t_emit<<<SZ_B * SZ_C, 256>>>(s2_, m2, i2, p2th, p2tl, SZ_C);

    // ---- final: out = gamma*pav + beta*(x @ p2) + 2*x ----
    gemm_hl<2, false><<<dim3(10, 8, SZ_B), 256, SMEM>>>(
        xh, xl, p2th, p2tl, out, nullptr, nullptr, pav_, x, gamma, beta,
        SZ_C, SZ_C, SZ_C, SZ_C, SZ_C,
        (long)SZ_N * SZ_C, (long)SZ_C * SZ_C, (long)SZ_N * SZ_C);
}

// round 15
// speedup vs baseline: 5.0032x; 1.1602x over previous
#include <cuda_runtime.h>
#include <cuda_bf16.h>
#include <cstdint>

// Problem shape: B=16, N=1024, C=1280, d=160
#define SZ_B   16
#define SZ_N   1024
#define SZ_C   1280
#define SZ_D   160
#define SZ_BN  (SZ_B * SZ_N)

typedef __nv_bfloat16 bf16;

// ---------------------------------------------------------------------------
// Scratch (static __device__ globals)
// ---------------------------------------------------------------------------
__device__ float g_s  [(size_t)SZ_B * SZ_N * SZ_N];
__device__ float g_s2 [(size_t)SZ_B * SZ_C * SZ_C];
__device__ float g_pav[(size_t)SZ_BN * SZ_C];
__device__ float g_m2 [(size_t)SZ_B * SZ_C];
__device__ float g_i2 [(size_t)SZ_B * SZ_C];

__device__ bf16 g_xh  [(size_t)SZ_BN * SZ_C];
__device__ bf16 g_xl  [(size_t)SZ_BN * SZ_C];
__device__ bf16 g_xth [(size_t)SZ_B * SZ_C * SZ_N];
__device__ bf16 g_xtl [(size_t)SZ_B * SZ_C * SZ_N];
__device__ bf16 g_wkqth[(size_t)2 * SZ_D * SZ_C];
__device__ bf16 g_wkqtl[(size_t)2 * SZ_D * SZ_C];
__device__ bf16 g_wvth[(size_t)SZ_C * SZ_C];
__device__ bf16 g_wvtl[(size_t)SZ_C * SZ_C];
__device__ bf16 g_kqh [(size_t)SZ_BN * 2 * SZ_D];
__device__ bf16 g_kql [(size_t)SZ_BN * 2 * SZ_D];
__device__ bf16 g_vth [(size_t)SZ_C * SZ_BN];
__device__ bf16 g_vtl [(size_t)SZ_C * SZ_BN];
__device__ bf16 g_ph  [(size_t)SZ_B * SZ_N * SZ_N];
__device__ bf16 g_pl  [(size_t)SZ_B * SZ_N * SZ_N];
__device__ bf16 g_p2th[(size_t)SZ_B * SZ_C * SZ_C];
__device__ bf16 g_p2tl[(size_t)SZ_B * SZ_C * SZ_C];

// ---------------------------------------------------------------------------
// PTX helpers
// ---------------------------------------------------------------------------
__device__ __forceinline__ uint32_t smem_u32(const void* p) {
    uint32_t a;
    asm("{ .reg .u64 t; cvta.to.shared.u64 t, %1; cvt.u32.u64 %0, t; }"
        : "=r"(a) : "l"(p));
    return a;
}
#define SWZ128(off) ((off) ^ (((off) >> 3) & 0x70))

__device__ __forceinline__ void ldsm4(uint32_t& a0, uint32_t& a1, uint32_t& a2,
                                      uint32_t& a3, uint32_t addr) {
    asm volatile("ldmatrix.sync.aligned.m8n8.x4.shared.b16 {%0,%1,%2,%3}, [%4];"
                 : "=r"(a0), "=r"(a1), "=r"(a2), "=r"(a3) : "r"(addr));
}
__device__ __forceinline__ void mma16816(float* c, const uint32_t* a,
                                         const uint32_t* b) {
    asm volatile(
        "mma.sync.aligned.m16n8k16.row.col.f32.bf16.bf16.f32 "
        "{%0,%1,%2,%3}, {%4,%5,%6,%7}, {%8,%9}, {%0,%1,%2,%3};"
        : "+f"(c[0]), "+f"(c[1]), "+f"(c[2]), "+f"(c[3])
        : "r"(a[0]), "r"(a[1]), "r"(a[2]), "r"(a[3]), "r"(b[0]), "r"(b[1]));
}
__device__ __forceinline__ void cp16(uint32_t dst, const void* src, int sz) {
    asm volatile("cp.async.cg.shared.global [%0], [%1], 16, %2;"
                 :: "r"(dst), "l"(src), "r"(sz));
}
#define CP_COMMIT() asm volatile("cp.async.commit_group;" ::: "memory")

__device__ __forceinline__ uint32_t pack_hi(float a, float b) {
    __nv_bfloat162 h; h.x = __float2bfloat16(a); h.y = __float2bfloat16(b);
    return *reinterpret_cast<uint32_t*>(&h);
}
__device__ __forceinline__ uint32_t pack_lo(float a, float b) {
    const bf16 ha = __float2bfloat16(a), hb = __float2bfloat16(b);
    __nv_bfloat162 l;
    l.x = __float2bfloat16(a - __bfloat162float(ha));
    l.y = __float2bfloat16(b - __bfloat162float(hb));
    return *reinterpret_cast<uint32_t*>(&l);
}

// ---------------------------------------------------------------------------
// Unified NT GEMM, bf16 hi/lo 3-term, cp.async 3-stage pipeline.
//   OM=0: fp32 out   OM=1: bf16 hi/lo out   OM=2: fused final epilogue
//   SYM : triangular grid + mirrored transposed store
//   Staging addresses hoisted out of the mainloop (gc = tid&7 invariant).
// ---------------------------------------------------------------------------
#define T_BYTES 16384
#define STG     65536
#define STAGES  3

template <int OM, bool SYM>
__global__ __launch_bounds__(256, 1)
void gemm_hl(const bf16* __restrict__ Ah, const bf16* __restrict__ Al,
             const bf16* __restrict__ Bh, const bf16* __restrict__ Bl,
             float* __restrict__ Cf, bf16* __restrict__ Ch, bf16* __restrict__ Cl,
             const float* __restrict__ Pv, const float* __restrict__ Xr,
             const float* __restrict__ gamma, const float* __restrict__ beta,
             int Ncols, int K, int lda, int ldb, int ldc,
             long sA, long sB, long sC)
{
    extern __shared__ char smem[];
    Ah += (long)blockIdx.z * sA;  Al += (long)blockIdx.z * sA;
    Bh += (long)blockIdx.z * sB;  Bl += (long)blockIdx.z * sB;
    if (OM == 0) Cf += (long)blockIdx.z * sC;
    if (OM == 1) { Ch += (long)blockIdx.z * sC; Cl += (long)blockIdx.z * sC; }
    if (OM == 2) { Cf += (long)blockIdx.z * sC; Pv += (long)blockIdx.z * sC;
                   Xr += (long)blockIdx.z * sC; }

    const int tid  = threadIdx.x;
    const int lane = tid & 31;
    const int wid  = tid >> 5;
    const int wm   = wid & 1;
    const int wn   = wid >> 1;

    int bx, by;
    if (SYM) {
        int t = blockIdx.x, b = 0;
        while ((b + 1) * (b + 2) / 2 <= t) b++;
        by = b; bx = t - b * (b + 1) / 2;
    } else { bx = blockIdx.x; by = blockIdx.y; }
    const int m0 = by * 128;
    const int n0 = bx * 128;

    const uint32_t sb = smem_u32(smem);
    const int nch = (K + 63) / 64;

    // ---- hoisted staging state (per-thread invariants) ----
    const int gc = tid & 7;                     // 16B granule within row
    uint32_t swz[4];
    const bf16 *pA[4], *pB[4];
    int szB[4];
    const long dAl = Al - Ah;
    const long dBl = Bl - Bh;
#pragma unroll
    for (int j = 0; j < 4; j++) {
        const int row = (tid >> 3) + j * 32;
        swz[j] = SWZ128((uint32_t)(row * 128 + gc * 16));
        pA[j] = Ah + (long)(m0 + row) * lda + gc * 8;
        pB[j] = Bh + (long)(n0 + row) * ldb + gc * 8;
        szB[j] = (n0 + row < Ncols) ? 16 : 0;
    }
    auto issue_stage = [&](int ch, int buf) {
        const int k0 = ch * 64;
        const uint32_t base = sb + buf * STG;
        const int kv = (k0 + gc * 8 < K) ? 16 : 0;
#pragma unroll
        for (int j = 0; j < 4; j++) {
            cp16(base + swz[j],               pA[j] + k0,       kv);
            cp16(base + T_BYTES + swz[j],     pA[j] + dAl + k0, kv);
            cp16(base + 2 * T_BYTES + swz[j], pB[j] + k0,       szB[j] & kv);
            cp16(base + 3 * T_BYTES + swz[j], pB[j] + dBl + k0, szB[j] & kv);
        }
        CP_COMMIT();
    };

    float acc[4][4][4];
#pragma unroll
    for (int i = 0; i < 4; i++)
#pragma unroll
        for (int j = 0; j < 4; j++)
#pragma unroll
            for (int u = 0; u < 4; u++) acc[i][j][u] = 0.f;

    for (int st = 0; st < STAGES && st < nch; st++) issue_stage(st, st);

    const int r8 = lane & 7;
    const int bhalf = (lane >> 3) & 1;
    const int bpair = (lane >> 4) & 1;
    const int g2 = lane >> 3;

    for (int ch = 0; ch < nch; ch++) {
        int pend = nch - 1 - ch;
        if (pend > STAGES - 1) pend = STAGES - 1;
        if (pend == 0)      asm volatile("cp.async.wait_group 0;" ::: "memory");
        else if (pend == 1) asm volatile("cp.async.wait_group 1;" ::: "memory");
        else                asm volatile("cp.async.wait_group 2;" ::: "memory");
        __syncthreads();

        const uint32_t aBh = sb + (ch % STAGES) * STG;
        const uint32_t aBl = aBh + T_BYTES;
        const uint32_t bBh = aBh + 2 * T_BYTES;
        const uint32_t bBl = aBh + 3 * T_BYTES;

#pragma unroll
        for (int kt = 0; kt < 4; kt++) {
            uint32_t bh[4][2], bl[4][2];
#pragma unroll
            for (int ntp = 0; ntp < 2; ntp++) {
                const int brow = wn * 32 + (ntp * 2 + bpair) * 8 + r8;
                const uint32_t boff =
                    SWZ128((uint32_t)(brow * 128 + (2 * kt + bhalf) * 16));
                ldsm4(bh[ntp * 2][0], bh[ntp * 2][1],
                      bh[ntp * 2 + 1][0], bh[ntp * 2 + 1][1], bBh + boff);
                ldsm4(bl[ntp * 2][0], bl[ntp * 2][1],
                      bl[ntp * 2 + 1][0], bl[ntp * 2 + 1][1], bBl + boff);
            }
#pragma unroll
            for (int mt = 0; mt < 4; mt++) {
                const int arow = wm * 64 + mt * 16 + (g2 & 1) * 8 + r8;
                const uint32_t aoff =
                    SWZ128((uint32_t)(arow * 128 + (2 * kt + (g2 >> 1)) * 16));
                uint32_t ah[4], al[4];
                ldsm4(ah[0], ah[1], ah[2], ah[3], aBh + aoff);
                ldsm4(al[0], al[1], al[2], al[3], aBl + aoff);
#pragma unroll
                for (int nt = 0; nt < 4; nt++) {
                    mma16816(acc[mt][nt], ah, bh[nt]);
                    mma16816(acc[mt][nt], ah, bl[nt]);
                    mma16816(acc[mt][nt], al, bh[nt]);
                }
            }
        }
        __syncthreads();
        if (ch + STAGES < nch) issue_stage(ch + STAGES, ch % STAGES);
    }

    float gv = 0.f, bv = 0.f;
    if (OM == 2) { gv = __ldg(gamma); bv = __ldg(beta); }

#pragma unroll
    for (int mt = 0; mt < 4; mt++) {
#pragma unroll
        for (int nt = 0; nt < 4; nt++) {
            const int row0 = m0 + wm * 64 + mt * 16 + (lane >> 2);
            const int col  = n0 + wn * 32 + nt * 8 + (lane & 3) * 2;
            if (col >= Ncols) continue;
            const long o0 = (long)row0 * ldc + col;
            const long o1 = (long)(row0 + 8) * ldc + col;
            if (OM == 0) {
                *reinterpret_cast<float2*>(Cf + o0) =
                    make_float2(acc[mt][nt][0], acc[mt][nt][1]);
                *reinterpret_cast<float2*>(Cf + o1) =
                    make_float2(acc[mt][nt][2], acc[mt][nt][3]);
            } else if (OM == 1) {
                *reinterpret_cast<uint32_t*>(Ch + o0) =
                    pack_hi(acc[mt][nt][0], acc[mt][nt][1]);
                *reinterpret_cast<uint32_t*>(Cl + o0) =
                    pack_lo(acc[mt][nt][0], acc[mt][nt][1]);
                *reinterpret_cast<uint32_t*>(Ch + o1) =
                    pack_hi(acc[mt][nt][2], acc[mt][nt][3]);
                *reinterpret_cast<uint32_t*>(Cl + o1) =
                    pack_lo(acc[mt][nt][2], acc[mt][nt][3]);
            } else {
                const float2 p0 = *reinterpret_cast<const float2*>(Pv + o0);
                const float2 x0 = *reinterpret_cast<const float2*>(Xr + o0);
                const float2 p1 = *reinterpret_cast<const float2*>(Pv + o1);
                const float2 x1 = *reinterpret_cast<const float2*>(Xr + o1);
                *reinterpret_cast<float2*>(Cf + o0) = make_float2(
                    gv * p0.x + bv * acc[mt][nt][0] + 2.f * x0.x,
                    gv * p0.y + bv * acc[mt][nt][1] + 2.f * x0.y);
                *reinterpret_cast<float2*>(Cf + o1) = make_float2(
                    gv * p1.x + bv * acc[mt][nt][2] + 2.f * x1.x,
                    gv * p1.y + bv * acc[mt][nt][3] + 2.f * x1.y);
            }
        }
    }

    if (SYM && bx != by) {
        __syncthreads();
        float* T = reinterpret_cast<float*>(smem);
#pragma unroll
        for (int mt = 0; mt < 4; mt++) {
#pragma unroll
            for (int nt = 0; nt < 4; nt++) {
                const int r0 = wm * 64 + mt * 16 + (lane >> 2);
                const int c  = wn * 32 + nt * 8 + (lane & 3) * 2;
                T[(c)     * 128 + r0]     = acc[mt][nt][0];
                T[(c + 1) * 128 + r0]     = acc[mt][nt][1];
                T[(c)     * 128 + r0 + 8] = acc[mt][nt][2];
                T[(c + 1) * 128 + r0 + 8] = acc[mt][nt][3];
            }
        }
        __syncthreads();
        for (int idx = tid; idx < 128 * 32; idx += 256) {
            const int row = idx >> 5, c4 = idx & 31;
            const float4 v = reinterpret_cast<const float4*>(T + row * 128)[c4];
            *reinterpret_cast<float4*>(Cf + (long)(n0 + row) * ldc + m0 + c4 * 4) = v;
        }
    }
}

// ---------------------------------------------------------------------------
// xprep: single read of x -> xh/xl (row layout) + xth/xtl (transposed), packed
// Grid (C/64, N/32, B), 256 threads. Tile 32 rows x 64 cols.
// ---------------------------------------------------------------------------
__global__ void xprep(const float* __restrict__ x,
                      bf16* __restrict__ xh, bf16* __restrict__ xl,
                      bf16* __restrict__ xth, bf16* __restrict__ xtl)
{
    __shared__ float t[32][66];
    const int b = blockIdx.z;
    const int n0 = blockIdx.y * 32;
    const int c0 = blockIdx.x * 64;
    const int tid = threadIdx.x;
    const int tx = tid & 31, ty = tid >> 5;
    const float* xb = x + (long)b * SZ_N * SZ_C;
    bf16* xhb = xh + (long)b * SZ_N * SZ_C;
    bf16* xlb = xl + (long)b * SZ_N * SZ_C;
    bf16* xthb = xth + (long)b * SZ_C * SZ_N;
    bf16* xtlb = xtl + (long)b * SZ_C * SZ_N;

#pragma unroll
    for (int i = 0; i < 32; i += 8) {
        const int r = n0 + ty + i;
        const int c = c0 + tx * 2;
        const float2 v = *reinterpret_cast<const float2*>(xb + (long)r * SZ_C + c);
        t[ty + i][tx * 2] = v.x;
        t[ty + i][tx * 2 + 1] = v.y;
        *reinterpret_cast<uint32_t*>(xhb + (long)r * SZ_C + c) = pack_hi(v.x, v.y);
        *reinterpret_cast<uint32_t*>(xlb + (long)r * SZ_C + c) = pack_lo(v.x, v.y);
    }
    __syncthreads();
#pragma unroll
    for (int it = 0; it < 2; it++) {
        const int w = it * 256 + tid;
        const int c = w >> 3;              // 0..63
        const int rg = (w & 7) * 4;        // 0..28
        const float v0 = t[rg][c], v1 = t[rg + 1][c];
        const float v2 = t[rg + 2][c], v3 = t[rg + 3][c];
        uint2 hh, ll;
        hh.x = pack_hi(v0, v1); hh.y = pack_hi(v2, v3);
        ll.x = pack_lo(v0, v1); ll.y = pack_lo(v2, v3);
        *reinterpret_cast<uint2*>(xthb + (long)(c0 + c) * SZ_N + n0 + rg) = hh;
        *reinterpret_cast<uint2*>(xtlb + (long)(c0 + c) * SZ_N + n0 + rg) = ll;
    }
}

// ---------------------------------------------------------------------------
// Transpose + split for weight matrices (ragged-safe, small)
// ---------------------------------------------------------------------------
__global__ void transpose_split(const float* __restrict__ in,
                                bf16* __restrict__ outH, bf16* __restrict__ outL,
                                int R, int Cc)
{
    __shared__ float t[32][33];
    const int c0 = blockIdx.x * 32, r0 = blockIdx.y * 32;
    const int tx = threadIdx.x & 31, ty = threadIdx.x >> 5;

#pragma unroll
    for (int i = 0; i < 32; i += 8) {
        const int r = r0 + ty + i, c = c0 + tx;
        t[ty + i][tx] = (r < R && c < Cc) ? in[(long)r * Cc + c] : 0.f;
    }
    __syncthreads();
#pragma unroll
    for (int i = 0; i < 32; i += 8) {
        const int c = c0 + ty + i, r = r0 + tx;
        if (c < Cc && r < R) {
            const float v = t[tx][ty + i];
            const bf16 h = __float2bfloat16(v);
            outH[(long)c * R + r] = h;
            outL[(long)c * R + r] = __float2bfloat16(v - __bfloat162float(h));
        }
    }
}

// ---------------------------------------------------------------------------
// Register-resident row softmax (L=1024): 1 global read, vectorized emit
// ---------------------------------------------------------------------------
__global__ void softmax_emit(const float* __restrict__ s, bf16* __restrict__ ph,
                             bf16* __restrict__ pl)
{
    const long row = blockIdx.x;
    const float4 v = reinterpret_cast<const float4*>(s + row * SZ_N)[threadIdx.x];
    const int tid = threadIdx.x;
    __shared__ float red[8];

    float m = fmaxf(fmaxf(v.x, v.y), fmaxf(v.z, v.w));
#pragma unroll
    for (int o = 16; o; o >>= 1) m = fmaxf(m, __shfl_xor_sync(0xffffffffu, m, o));
    if ((tid & 31) == 0) red[tid >> 5] = m;
    __syncthreads();
    m = red[0];
#pragma unroll
    for (int w = 1; w < 8; w++) m = fmaxf(m, red[w]);

    const float e0 = __expf(v.x - m), e1 = __expf(v.y - m);
    const float e2 = __expf(v.z - m), e3 = __expf(v.w - m);
    float sum = e0 + e1 + e2 + e3;
#pragma unroll
    for (int o = 16; o; o >>= 1) sum += __shfl_xor_sync(0xffffffffu, sum, o);
    __syncthreads();
    if ((tid & 31) == 0) red[tid >> 5] = sum;
    __syncthreads();
    sum = 0.f;
#pragma unroll
    for (int w = 0; w < 8; w++) sum += red[w];
    const float inv = 1.0f / sum;

    const float p0 = e0 * inv, p1 = e1 * inv, p2 = e2 * inv, p3 = e3 * inv;
    uint2 hh, ll;
    hh.x = pack_hi(p0, p1); hh.y = pack_hi(p2, p3);
    ll.x = pack_lo(p0, p1); ll.y = pack_lo(p2, p3);
    reinterpret_cast<uint2*>(ph + row * SZ_N)[tid] = hh;
    reinterpret_cast<uint2*>(pl + row * SZ_N)[tid] = ll;
}

// ---------------------------------------------------------------------------
// Register-resident row stats for s2 (L=1280): 1 global read
// ---------------------------------------------------------------------------
__global__ void rowstats(const float* __restrict__ s2, float* __restrict__ mArr,
                         float* __restrict__ iArr)
{
    const long row = blockIdx.x;
    const float* p = s2 + row * SZ_C;
    const int tid = threadIdx.x;
    __shared__ float red[8];

    const float4 v = reinterpret_cast<const float4*>(p)[tid];
    const float v4 = p[1024 + tid];

    float m = fmaxf(fmaxf(fmaxf(v.x, v.y), fmaxf(v.z, v.w)), v4);
#pragma unroll
    for (int o = 16; o; o >>= 1) m = fmaxf(m, __shfl_xor_sync(0xffffffffu, m, o));
    if ((tid & 31) == 0) red[tid >> 5] = m;
    __syncthreads();
    m = red[0];
#pragma unroll
    for (int w = 1; w < 8; w++) m = fmaxf(m, red[w]);

    float sum = __expf(v.x - m) + __expf(v.y - m) + __expf(v.z - m)
              + __expf(v.w - m) + __expf(v4 - m);
#pragma unroll
    for (int o = 16; o; o >>= 1) sum += __shfl_xor_sync(0xffffffffu, sum, o);
    __syncthreads();
    if ((tid & 31) == 0) red[tid >> 5] = sum;
    __syncthreads();
    sum = 0.f;
#pragma unroll
    for (int w = 0; w < 8; w++) sum += red[w];

    if (tid == 0) { mArr[row] = m; iArr[row] = 1.0f / sum; }
}

// p2T[b][e][c] = exp(s2[b][e][c] - m[b][c]) * inv[b][c]  (vectorized emit)
__global__ void p2t_emit(const float* __restrict__ s2,
                         const float* __restrict__ mArr,
                         const float* __restrict__ iArr,
                         bf16* __restrict__ th, bf16* __restrict__ tl)
{
    const long r = blockIdx.x;
    const long b = r / SZ_C;
    const float4* p4 = reinterpret_cast<const float4*>(s2 + r * SZ_C);
    const float4* m4 = reinterpret_cast<const float4*>(mArr + b * SZ_C);
    const float4* i4 = reinterpret_cast<const float4*>(iArr + b * SZ_C);
    uint2* oh = reinterpret_cast<uint2*>(th + r * SZ_C);
    uint2* ol = reinterpret_cast<uint2*>(tl + r * SZ_C);
    for (int c4 = threadIdx.x; c4 < SZ_C / 4; c4 += 256) {
        const float4 v = p4[c4];
        const float4 mm = __ldg(m4 + c4);
        const float4 ii = __ldg(i4 + c4);
        const float e0 = __expf(v.x - mm.x) * ii.x;
        const float e1 = __expf(v.y - mm.y) * ii.y;
        const float e2 = __expf(v.z - mm.z) * ii.z;
        const float e3 = __expf(v.w - mm.w) * ii.w;
        uint2 hh, ll;
        hh.x = pack_hi(e0, e1); hh.y = pack_hi(e2, e3);
        ll.x = pack_lo(e0, e1); ll.y = pack_lo(e2, e3);
        oh[c4] = hh;
        ol[c4] = ll;
    }
}

// ---------------------------------------------------------------------------
// kernel_launch
// ---------------------------------------------------------------------------
extern "C" void kernel_launch(void* const* d_in, const int* in_sizes, int n_in,
                              void* d_out, int out_size)
{
    const float* x     = (const float*)d_in[0];
    const float* Wk    = (const float*)d_in[1];
    const float* Wq    = (const float*)d_in[2];
    const float* Wv    = (const float*)d_in[3];
    const float* gamma = (const float*)d_in[4];
    const float* beta  = (const float*)d_in[5];
    float* out = (float*)d_out;

    float *s_, *s2_, *pav_, *m2, *i2;
    bf16 *xh, *xl, *xth, *xtl, *wkqth, *wkqtl, *wvth, *wvtl;
    bf16 *kqh, *kql, *vth, *vtl, *ph, *pl, *p2th, *p2tl;
    cudaGetSymbolAddress((void**)&s_,    g_s);
    cudaGetSymbolAddress((void**)&s2_,   g_s2);
    cudaGetSymbolAddress((void**)&pav_,  g_pav);
    cudaGetSymbolAddress((void**)&m2,    g_m2);
    cudaGetSymbolAddress((void**)&i2,    g_i2);
    cudaGetSymbolAddress((void**)&xh,    g_xh);
    cudaGetSymbolAddress((void**)&xl,    g_xl);
    cudaGetSymbolAddress((void**)&xth,   g_xth);
    cudaGetSymbolAddress((void**)&xtl,   g_xtl);
    cudaGetSymbolAddress((void**)&wkqth, g_wkqth);
    cudaGetSymbolAddress((void**)&wkqtl, g_wkqtl);
    cudaGetSymbolAddress((void**)&wvth,  g_wvth);
    cudaGetSymbolAddress((void**)&wvtl,  g_wvtl);
    cudaGetSymbolAddress((void**)&kqh,   g_kqh);
    cudaGetSymbolAddress((void**)&kql,   g_kql);
    cudaGetSymbolAddress((void**)&vth,   g_vth);
    cudaGetSymbolAddress((void**)&vtl,   g_vtl);
    cudaGetSymbolAddress((void**)&ph,    g_ph);
    cudaGetSymbolAddress((void**)&pl,    g_pl);
    cudaGetSymbolAddress((void**)&p2th,  g_p2th);
    cudaGetSymbolAddress((void**)&p2tl,  g_p2tl);

    constexpr int SMEM = STAGES * STG;
    cudaFuncSetAttribute((const void*)gemm_hl<0, false>,
                         cudaFuncAttributeMaxDynamicSharedMemorySize, SMEM);
    cudaFuncSetAttribute((const void*)gemm_hl<0, true>,
                         cudaFuncAttributeMaxDynamicSharedMemorySize, SMEM);
    cudaFuncSetAttribute((const void*)gemm_hl<1, false>,
                         cudaFuncAttributeMaxDynamicSharedMemorySize, SMEM);
    cudaFuncSetAttribute((const void*)gemm_hl<2, false>,
                         cudaFuncAttributeMaxDynamicSharedMemorySize, SMEM);

    // ---- operand preparation (single read of x) ----
    xprep<<<dim3(SZ_C / 64, SZ_N / 32, SZ_B), 256>>>(x, xh, xl, xth, xtl);
    transpose_split<<<dim3(5, 40, 1), 256>>>(Wk, wkqth, wkqtl, SZ_C, SZ_D);
    transpose_split<<<dim3(5, 40, 1), 256>>>(
        Wq, wkqth + (size_t)SZ_D * SZ_C, wkqtl + (size_t)SZ_D * SZ_C, SZ_C, SZ_D);
    transpose_split<<<dim3(40, 40, 1), 256>>>(Wv, wvth, wvtl, SZ_C, SZ_C);

    // ---- fused kq projection ----
    gemm_hl<1, false><<<dim3(3, 128, 1), 256, SMEM>>>(
        xh, xl, wkqth, wkqtl, nullptr, kqh, kql, nullptr, nullptr, nullptr, nullptr,
        2 * SZ_D, SZ_C, SZ_C, SZ_C, 2 * SZ_D, 0, 0, 0);

    // ---- vT = Wv^T @ x^T (direct transposed split output) ----
    gemm_hl<1, false><<<dim3(128, 10, 1), 256, SMEM>>>(
        wvth, wvtl, xh, xl, nullptr, vth, vtl, nullptr, nullptr, nullptr, nullptr,
        SZ_BN, SZ_C, SZ_C, SZ_C, SZ_BN, 0, 0, 0);

    // ---- s = k @ q^T ----
    gemm_hl<0, false><<<dim3(8, 8, SZ_B), 256, SMEM>>>(
        kqh, kql, kqh + SZ_D, kql + SZ_D, s_, nullptr, nullptr,
        nullptr, nullptr, nullptr, nullptr,
        SZ_N, SZ_D, 2 * SZ_D, 2 * SZ_D, SZ_N,
        (long)SZ_N * 2 * SZ_D, (long)SZ_N * 2 * SZ_D, (long)SZ_N * SZ_N);
    softmax_emit<<<SZ_B * SZ_N, 256>>>(s_, ph, pl);

    // ---- pav = p @ v ----
    gemm_hl<0, false><<<dim3(10, 8, SZ_B), 256, SMEM>>>(
        ph, pl, vth, vtl, pav_, nullptr, nullptr, nullptr, nullptr, nullptr, nullptr,
        SZ_C, SZ_N, SZ_N, SZ_BN, SZ_C,
        (long)SZ_N * SZ_N, (long)SZ_N, (long)SZ_N * SZ_C);

    // ---- s2 = x^T @ x (triangular) -> stats -> p2T ----
    gemm_hl<0, true><<<dim3(55, 1, SZ_B), 256, SMEM>>>(
        xth, xtl, xth, xtl, s2_, nullptr, nullptr, nullptr, nullptr, nullptr, nullptr,
        SZ_C, SZ_N, SZ_N, SZ_N, SZ_C,
        (long)SZ_C * SZ_N, (long)SZ_C * SZ_N, (long)SZ_C * SZ_C);
    rowstats<<<SZ_B * SZ_C, 256>>>(s2_, m2, i2);
    p2t_emit<<<SZ_B * SZ_C, 256>>>(s2_, m2, i2, p2th, p2tl);

    // ---- final: out = gamma*pav + beta*(x @ p2) + 2*x ----
    gemm_hl<2, false><<<dim3(10, 8, SZ_B), 256, SMEM>>>(
        xh, xl, p2th, p2tl, out, nullptr, nullptr, pav_, x, gamma, beta,
        SZ_C, SZ_C, SZ_C, SZ_C, SZ_C,
        (long)SZ_N * SZ_C, (long)SZ_C * SZ_C, (long)SZ_N * SZ_C);
}